// round 3
// baseline (speedup 1.0000x reference)
#include <cuda_runtime.h>
#include <cuda_fp16.h>
#include <cstdint>
#include <cstddef>

#define DI __device__ __forceinline__

static constexpr int NB  = 256;     // batch
static constexpr int CAT = 1024;
static constexpr int HD  = 512;
static constexpr int VOC = 32000;
static constexpr int TT  = 8;
static constexpr int G4  = 4 * HD;  // 2048

// ---------------- device scratch (static: no allocation) ----------------
__device__ __half d_ctxin_hi[NB * CAT];
__device__ __half d_ctxin_lo[NB * CAT];
__device__ __half d_wm_hi[HD * CAT];
__device__ __half d_wm_lo[HD * CAT];
__device__ __half d_wih_hi[G4 * HD];   // gate-interleaved rows
__device__ __half d_wih_lo[G4 * HD];   // gate-interleaved rows
__device__ __half d_whhp[G4 * HD];     // gate-interleaved rows
__device__ __half d_wo16[VOC * HD];
__device__ float  d_bihp[G4];          // permuted b_ih
__device__ float  d_bhhp[G4];          // permuted b_hh
__device__ float  d_ctx32[NB * HD];
__device__ __half d_ctx_hi[NB * HD];
__device__ __half d_ctx_lo[NB * HD];
__device__ float  d_xproj[NB * G4];    // gate-interleaved cols
__device__ float  d_cst[NB * HD];
__device__ __half d_h_hi[NB * HD];
__device__ __half d_h_lo[NB * HD];
__device__ __half d_hall[NB * TT * HD];

// ---------------- PTX helpers ----------------
DI uint32_t smem_u32(const void* p) {
    uint32_t a;
    asm("{ .reg .u64 t; cvta.to.shared.u64 t, %1; cvt.u32.u64 %0, t; }"
        : "=r"(a) : "l"(p));
    return a;
}
DI void cp_async16(uint32_t dst, const void* src) {
    asm volatile("cp.async.cg.shared.global [%0], [%1], 16;"
                 :: "r"(dst), "l"(src) : "memory");
}
DI void cp_commit() { asm volatile("cp.async.commit_group;" ::: "memory"); }
template <int N>
DI void cp_wait() { asm volatile("cp.async.wait_group %0;" :: "n"(N) : "memory"); }

DI void ldsm_x4(uint32_t (&d)[4], uint32_t addr) {
    asm volatile("ldmatrix.sync.aligned.m8n8.x4.shared.b16 {%0,%1,%2,%3}, [%4];"
                 : "=r"(d[0]), "=r"(d[1]), "=r"(d[2]), "=r"(d[3]) : "r"(addr));
}
DI void mma16816(float (&c)[4], const uint32_t (&a)[4], uint32_t b0, uint32_t b1) {
    asm volatile(
        "mma.sync.aligned.m16n8k16.row.col.f32.f16.f16.f32 "
        "{%0,%1,%2,%3}, {%4,%5,%6,%7}, {%8,%9}, {%0,%1,%2,%3};"
        : "+f"(c[0]), "+f"(c[1]), "+f"(c[2]), "+f"(c[3])
        : "r"(a[0]), "r"(a[1]), "r"(a[2]), "r"(a[3]), "r"(b0), "r"(b1));
}

DI void split1(float v, __half& hi, __half& lo) {
    __half h = __float2half_rn(v);
    hi = h;
    lo = __float2half_rn(v - __half2float(h));
}
DI void split4(float4 v, __half2* hi2, __half2* lo2) {
    __half2 h01 = __floats2half2_rn(v.x, v.y);
    __half2 h23 = __floats2half2_rn(v.z, v.w);
    float2 f01 = __half22float2(h01);
    float2 f23 = __half22float2(h23);
    hi2[0] = h01; hi2[1] = h23;
    lo2[0] = __floats2half2_rn(v.x - f01.x, v.y - f01.y);
    lo2[1] = __floats2half2_rn(v.z - f23.x, v.w - f23.y);
}

// ---------------- merged conversion / permutation kernel ----------------
// Regions (in float4 units):
//  R0: context split            NB*CAT/4
//  R1: W_merge split            HD*CAT/4
//  R2: W_ih split + perm        G4*HD/4
//  R3: W_hh cvt + perm          G4*HD/4
//  R4: W_out cvt                VOC*HD/4
// Biases handled by block 0.
__global__ void k_prep(const float4* __restrict__ ctx, const float4* __restrict__ wm,
                       const float* __restrict__ wih, const float* __restrict__ whh,
                       const float4* __restrict__ wo,
                       const float* __restrict__ bih, const float* __restrict__ bhh) {
    constexpr int R0 = NB * CAT / 4;
    constexpr int R1 = R0 + HD * CAT / 4;
    constexpr int R2 = R1 + G4 * HD / 4;
    constexpr int R3 = R2 + G4 * HD / 4;
    constexpr int R4 = R3 + VOC * HD / 4;
    constexpr int HD4 = HD / 4;

    if (blockIdx.x == 0) {
        for (int p = threadIdx.x; p < G4; p += blockDim.x) {
            int j = p >> 2, q = p & 3;
            d_bihp[p] = bih[q * HD + j];
            d_bhhp[p] = bhh[q * HD + j];
        }
    }
    int stride = gridDim.x * blockDim.x;
    for (int u = blockIdx.x * blockDim.x + threadIdx.x; u < R4; u += stride) {
        if (u < R0) {
            split4(ctx[u], (__half2*)d_ctxin_hi + 2 * u, (__half2*)d_ctxin_lo + 2 * u);
        } else if (u < R1) {
            int v = u - R0;
            split4(wm[v], (__half2*)d_wm_hi + 2 * v, (__half2*)d_wm_lo + 2 * v);
        } else if (u < R2) {
            int v = u - R1;                       // new-layout float4 index
            int p = v >> 7, c4 = v & (HD4 - 1);   // new row p, col group
            int j = p >> 2, q = p & 3;
            float4 w = *reinterpret_cast<const float4*>(wih + (size_t)(q * HD + j) * HD + c4 * 4);
            split4(w, (__half2*)d_wih_hi + 2 * v, (__half2*)d_wih_lo + 2 * v);
        } else if (u < R3) {
            int v = u - R2;
            int p = v >> 7, c4 = v & (HD4 - 1);
            int j = p >> 2, q = p & 3;
            float4 w = *reinterpret_cast<const float4*>(whh + (size_t)(q * HD + j) * HD + c4 * 4);
            __half2* o = (__half2*)d_whhp + 2 * v;
            o[0] = __floats2half2_rn(w.x, w.y);
            o[1] = __floats2half2_rn(w.z, w.w);
        } else {
            int v = u - R3;
            float4 w = wo[v];
            __half2* o = (__half2*)d_wo16 + 2 * v;
            o[0] = __floats2half2_rn(w.x, w.y);
            o[1] = __floats2half2_rn(w.z, w.w);
        }
    }
}

__global__ void k_split(const float* __restrict__ x, __half* __restrict__ hi,
                        __half* __restrict__ lo, int n) {
    int i = blockIdx.x * blockDim.x + threadIdx.x;
    if (i < n) split1(x[i], hi[i], lo[i]);
}

// ---------------- HMMA f16 GEMM (generic): C = sum_p A_p@B_p^T + bias ------
// CTA tile 128x128, K-chunk 64, 256 threads, 2-stage cp.async double buffer.
template <int NPASS>
__global__ void __launch_bounds__(256)
k_gemm(float* __restrict__ C, int ldc,
       const __half* __restrict__ A0, const __half* __restrict__ A1,
       const __half* __restrict__ A2,
       const __half* __restrict__ B0, const __half* __restrict__ B1,
       const __half* __restrict__ B2,
       const float* __restrict__ bias, int K) {
    extern __shared__ char smem[];
    constexpr int TILE_B = 128 * 128;
    constexpr int STG    = 2 * TILE_B;

    const uint32_t sb = smem_u32(smem);
    const int tid    = threadIdx.x;
    const int lane   = tid & 31;
    const int wid    = tid >> 5;
    const int warp_m = wid & 3;
    const int warp_n = wid >> 2;

    const __half* Ap[3] = {A0, A1, A2};
    const __half* Bp[3] = {B0, B1, B2};

    const int mBase = blockIdx.y * 128;
    const int nBase = blockIdx.x * 128;
    const int kch   = K >> 6;
    const int total = NPASS * kch;

    const int ldr = tid >> 3;
    const int ldg = tid & 7;

    auto load_chunk = [&](int ch) {
        const int st   = ch & 1;
        const int pass = ch / kch;
        const int kc   = ch - pass * kch;
        const __half* Ag = Ap[pass] + (size_t)mBase * K + kc * 64;
        const __half* Bg = Bp[pass] + (size_t)nBase * K + kc * 64;
        const uint32_t a_u = sb + st * STG;
        const uint32_t b_u = a_u + TILE_B;
#pragma unroll
        for (int it = 0; it < 4; ++it) {
            int r = ldr + it * 32;
            uint32_t off = (uint32_t)(r * 128 + (ldg * 16 ^ ((r & 7) << 4)));
            cp_async16(a_u + off, Ag + (size_t)r * K + ldg * 8);
            cp_async16(b_u + off, Bg + (size_t)r * K + ldg * 8);
        }
        cp_commit();
    };

    float acc[2][8][4];
#pragma unroll
    for (int mi = 0; mi < 2; ++mi)
#pragma unroll
        for (int ni = 0; ni < 8; ++ni)
#pragma unroll
            for (int q = 0; q < 4; ++q) acc[mi][ni][q] = 0.f;

    int arow[2], brow[4];
#pragma unroll
    for (int mi = 0; mi < 2; ++mi)
        arow[mi] = warp_m * 32 + mi * 16 + (lane & 7) + ((lane >> 3) & 1) * 8;
#pragma unroll
    for (int nq = 0; nq < 4; ++nq)
        brow[nq] = warp_n * 64 + nq * 16 + (lane & 7) + (lane >> 4) * 8;
    const int akb = (lane >> 4) * 16;
    const int bkb = ((lane >> 3) & 1) * 16;

    load_chunk(0);

    for (int ch = 0; ch < total; ++ch) {
        if (ch + 1 < total) { load_chunk(ch + 1); cp_wait<1>(); }
        else                { cp_wait<0>(); }
        __syncthreads();

        const uint32_t a_u = sb + (ch & 1) * STG;
        const uint32_t b_u = a_u + TILE_B;

#pragma unroll
        for (int ks = 0; ks < 4; ++ks) {
            uint32_t aF[2][4];
#pragma unroll
            for (int mi = 0; mi < 2; ++mi) {
                int r = arow[mi], kb = ks * 32 + akb;
                ldsm_x4(aF[mi], a_u + r * 128 + (kb ^ ((r & 7) << 4)));
            }
            uint32_t bF[4][4];
#pragma unroll
            for (int nq = 0; nq < 4; ++nq) {
                int r = brow[nq], kb = ks * 32 + bkb;
                ldsm_x4(bF[nq], b_u + r * 128 + (kb ^ ((r & 7) << 4)));
            }
#pragma unroll
            for (int mi = 0; mi < 2; ++mi)
#pragma unroll
                for (int ni = 0; ni < 8; ++ni)
                    mma16816(acc[mi][ni], aF[mi],
                             bF[ni >> 1][(ni & 1) * 2], bF[ni >> 1][(ni & 1) * 2 + 1]);
        }
        __syncthreads();
    }

    const int m0 = mBase + warp_m * 32;
    const int n0 = nBase + warp_n * 64;
#pragma unroll
    for (int ni = 0; ni < 8; ++ni) {
        int col = n0 + ni * 8 + 2 * (lane & 3);
        float2 bv = *reinterpret_cast<const float2*>(bias + col);
#pragma unroll
        for (int mi = 0; mi < 2; ++mi) {
            int row = m0 + mi * 16 + (lane >> 2);
            float2 v0 = {acc[mi][ni][0] + bv.x, acc[mi][ni][1] + bv.y};
            float2 v1 = {acc[mi][ni][2] + bv.x, acc[mi][ni][3] + bv.y};
            *reinterpret_cast<float2*>(C + (size_t)row * ldc + col) = v0;
            *reinterpret_cast<float2*>(C + (size_t)(row + 8) * ldc + col) = v1;
        }
    }
}

// ---------------- fused LSTM step: gates GEMM + cell epilogue --------------
// gates[n,p] = xproj[n,p] + (h @ Whh_p^T)[n,p] + bhh_p[p], p = gate-interleaved.
// CTA tile M=64 (batch) x N=64 (gate cols) = 16 hidden units; 128 threads.
// NPASS=2: A passes {h_hi, h_lo}; NPASS=0: t=0, skip GEMM entirely.
template <int NPASS>
__global__ void __launch_bounds__(128)
k_step(const __half* __restrict__ Ahi, const __half* __restrict__ Alo,
       const __half* __restrict__ Bw,
       const float* __restrict__ xproj, const float* __restrict__ bhhp,
       float* __restrict__ cst, __half* __restrict__ hhi, __half* __restrict__ hlo,
       __half* __restrict__ hall, int t) {
    extern __shared__ char smem[];
    constexpr int TILE_B = 64 * 128;   // 64 rows x 64 halfs = 8 KB
    constexpr int STG    = 2 * TILE_B;

    const int tid    = threadIdx.x;
    const int lane   = tid & 31;
    const int wid    = tid >> 5;
    const int warp_m = wid & 1;
    const int warp_n = wid >> 1;

    const int mBase = blockIdx.y * 64;
    const int nBase = blockIdx.x * 64;

    float acc[2][4][4];
#pragma unroll
    for (int mi = 0; mi < 2; ++mi)
#pragma unroll
        for (int ni = 0; ni < 4; ++ni)
#pragma unroll
            for (int q = 0; q < 4; ++q) acc[mi][ni][q] = 0.f;

    if (NPASS > 0) {
        const uint32_t sb = smem_u32(smem);
        const __half* Ap[2] = {Ahi, Alo};
        const int kch   = HD >> 6;        // 8
        const int total = NPASS * kch;    // 16

        const int ldr = tid >> 3;         // 0..15
        const int ldg = tid & 7;

        auto load_chunk = [&](int ch) {
            const int st   = ch & 1;
            const int pass = ch >> 3;
            const int kc   = ch & 7;
            const __half* Ag = Ap[pass] + (size_t)mBase * HD + kc * 64;
            const __half* Bg = Bw + (size_t)nBase * HD + kc * 64;
            const uint32_t a_u = sb + st * STG;
            const uint32_t b_u = a_u + TILE_B;
#pragma unroll
            for (int it = 0; it < 4; ++it) {
                int r = ldr + it * 16;
                uint32_t off = (uint32_t)(r * 128 + (ldg * 16 ^ ((r & 7) << 4)));
                cp_async16(a_u + off, Ag + (size_t)r * HD + ldg * 8);
                cp_async16(b_u + off, Bg + (size_t)r * HD + ldg * 8);
            }
            cp_commit();
        };

        int arow[2], brow[2];
#pragma unroll
        for (int mi = 0; mi < 2; ++mi)
            arow[mi] = warp_m * 32 + mi * 16 + (lane & 7) + ((lane >> 3) & 1) * 8;
#pragma unroll
        for (int nq = 0; nq < 2; ++nq)
            brow[nq] = warp_n * 32 + nq * 16 + (lane & 7) + (lane >> 4) * 8;
        const int akb = (lane >> 4) * 16;
        const int bkb = ((lane >> 3) & 1) * 16;

        load_chunk(0);
        for (int ch = 0; ch < total; ++ch) {
            if (ch + 1 < total) { load_chunk(ch + 1); cp_wait<1>(); }
            else                { cp_wait<0>(); }
            __syncthreads();
            const uint32_t a_u = sb + (ch & 1) * STG;
            const uint32_t b_u = a_u + TILE_B;
#pragma unroll
            for (int ks = 0; ks < 4; ++ks) {
                uint32_t aF[2][4];
#pragma unroll
                for (int mi = 0; mi < 2; ++mi) {
                    int r = arow[mi], kb = ks * 32 + akb;
                    ldsm_x4(aF[mi], a_u + r * 128 + (kb ^ ((r & 7) << 4)));
                }
                uint32_t bF[2][4];
#pragma unroll
                for (int nq = 0; nq < 2; ++nq) {
                    int r = brow[nq], kb = ks * 32 + bkb;
                    ldsm_x4(bF[nq], b_u + r * 128 + (kb ^ ((r & 7) << 4)));
                }
#pragma unroll
                for (int mi = 0; mi < 2; ++mi)
#pragma unroll
                    for (int ni = 0; ni < 4; ++ni)
                        mma16816(acc[mi][ni], aF[mi],
                                 bF[ni >> 1][(ni & 1) * 2], bF[ni >> 1][(ni & 1) * 2 + 1]);
            }
            __syncthreads();
        }
    }

    // ---- cell epilogue ----
    const int m0  = mBase + warp_m * 32;
    const int n0g = nBase + warp_n * 32;   // gate-col base
    const int a   = lane & 3;
    const int rb  = lane >> 2;

#pragma unroll
    for (int ni = 0; ni < 4; ++ni) {
        int col = n0g + ni * 8 + 2 * a;
        float2 bb = *reinterpret_cast<const float2*>(bhhp + col);
#pragma unroll
        for (int mi = 0; mi < 2; ++mi) {
#pragma unroll
            for (int hq = 0; hq < 2; ++hq) {
                int row = m0 + mi * 16 + rb + hq * 8;
                float2 xp = *reinterpret_cast<const float2*>(xproj + (size_t)row * G4 + col);
                float g0 = acc[mi][ni][hq * 2 + 0] + xp.x + bb.x;
                float g1 = acc[mi][ni][hq * 2 + 1] + xp.y + bb.y;
                float o0 = __shfl_xor_sync(0xFFFFFFFFu, g0, 1);
                float o1 = __shfl_xor_sync(0xFFFFFFFFu, g1, 1);
                if ((a & 1) == 0) {
                    // this thread: (i, f); partner: (g, o)
                    float si = 1.f / (1.f + expf(-g0));
                    float sf = 1.f / (1.f + expf(-g1));
                    float tg = tanhf(o0);
                    float so = 1.f / (1.f + expf(-o1));
                    int j = (n0g >> 2) + 2 * ni + (a >> 1);
                    float cp = (NPASS == 0) ? 0.f : cst[(size_t)row * HD + j];
                    float cn = sf * cp + si * tg;
                    cst[(size_t)row * HD + j] = cn;
                    float h = so * tanhf(cn);
                    __half hh = __float2half_rn(h);
                    hhi[(size_t)row * HD + j] = hh;
                    hlo[(size_t)row * HD + j] = __float2half_rn(h - __half2float(hh));
                    hall[((size_t)row * TT + t) * HD + j] = hh;
                }
            }
        }
    }
}

// ---------------- host orchestration ----------------
extern "C" void kernel_launch(void* const* d_in, const int* in_sizes, int n_in,
                              void* d_out, int out_size) {
    const float* context = (const float*)d_in[0];
    const float* W_merge = (const float*)d_in[1];
    const float* b_merge = (const float*)d_in[2];
    const float* W_ih    = (const float*)d_in[3];
    const float* W_hh    = (const float*)d_in[4];
    const float* b_ih    = (const float*)d_in[5];
    const float* b_hh    = (const float*)d_in[6];
    const float* W_out   = (const float*)d_in[7];
    const float* b_out   = (const float*)d_in[8];
    float* out = (float*)d_out;

    __half *ctxin_hi, *ctxin_lo, *wm_hi, *wm_lo, *wih_hi, *wih_lo, *whhp, *wo16;
    __half *ctx_hi, *ctx_lo, *h_hi, *h_lo, *hall;
    float *ctx32, *xproj, *cbuf, *bihp, *bhhp;
    cudaGetSymbolAddress((void**)&ctxin_hi, d_ctxin_hi);
    cudaGetSymbolAddress((void**)&ctxin_lo, d_ctxin_lo);
    cudaGetSymbolAddress((void**)&wm_hi, d_wm_hi);
    cudaGetSymbolAddress((void**)&wm_lo, d_wm_lo);
    cudaGetSymbolAddress((void**)&wih_hi, d_wih_hi);
    cudaGetSymbolAddress((void**)&wih_lo, d_wih_lo);
    cudaGetSymbolAddress((void**)&whhp, d_whhp);
    cudaGetSymbolAddress((void**)&wo16, d_wo16);
    cudaGetSymbolAddress((void**)&bihp, d_bihp);
    cudaGetSymbolAddress((void**)&bhhp, d_bhhp);
    cudaGetSymbolAddress((void**)&ctx32, d_ctx32);
    cudaGetSymbolAddress((void**)&ctx_hi, d_ctx_hi);
    cudaGetSymbolAddress((void**)&ctx_lo, d_ctx_lo);
    cudaGetSymbolAddress((void**)&xproj, d_xproj);
    cudaGetSymbolAddress((void**)&cbuf, d_cst);
    cudaGetSymbolAddress((void**)&h_hi, d_h_hi);
    cudaGetSymbolAddress((void**)&h_lo, d_h_lo);
    cudaGetSymbolAddress((void**)&hall, d_hall);

    const int SMEM = 2 * 2 * 128 * 128;  // 65536
    cudaFuncSetAttribute(k_gemm<1>, cudaFuncAttributeMaxDynamicSharedMemorySize, SMEM);
    cudaFuncSetAttribute(k_gemm<3>, cudaFuncAttributeMaxDynamicSharedMemorySize, SMEM);

    // one merged conversion + permutation kernel
    k_prep<<<2048, 256>>>((const float4*)context, (const float4*)W_merge,
                          W_ih, W_hh, (const float4*)W_out, b_ih, b_hh);

    // GEMM1: ctx = context @ Wm^T + b_merge   (3-pass split-fp16 ~ fp32)
    {
        dim3 g(HD / 128, NB / 128);  // (4,2)
        k_gemm<3><<<g, 256, SMEM>>>(ctx32, HD,
            ctxin_hi, ctxin_lo, ctxin_hi,
            wm_hi, wm_hi, wm_lo,
            b_merge, CAT);
    }
    k_split<<<(NB * HD + 255) / 256, 256>>>(ctx32, ctx_hi, ctx_lo, NB * HD);
    // GEMM2: x_proj(perm) = ctx @ Wih_p^T + b_ih_p   (3-pass)
    {
        dim3 g(G4 / 128, NB / 128);  // (16,2)
        k_gemm<3><<<g, 256, SMEM>>>(xproj, G4,
            ctx_hi, ctx_lo, ctx_hi,
            wih_hi, wih_hi, wih_lo,
            bihp, HD);
    }
    // LSTM recurrence: one fused kernel per step
    {
        dim3 g(G4 / 64, NB / 64);  // (32,4) = 128 CTAs
        const int SMS = 2 * 2 * 64 * 128;  // 32768
        k_step<0><<<g, 128, 0>>>(h_hi, h_lo, whhp, xproj, bhhp,
                                 cbuf, h_hi, h_lo, hall, 0);
        for (int t = 1; t < TT; ++t)
            k_step<2><<<g, 128, SMS>>>(h_hi, h_lo, whhp, xproj, bhhp,
                                       cbuf, h_hi, h_lo, hall, t);
    }
    // Big GEMM: out[2048,32000] = H_all @ Wo^T + b_out
    {
        dim3 g(VOC / 128, (NB * TT) / 128);  // (250,16)
        k_gemm<1><<<g, 256, SMEM>>>(out, VOC,
            hall, hall, hall,
            wo16, wo16, wo16,
            b_out, HD);
    }
}

// round 4
// speedup vs baseline: 1.1875x; 1.1875x over previous
#include <cuda_runtime.h>
#include <cuda_fp16.h>
#include <cstdint>
#include <cstddef>

#define DI __device__ __forceinline__

static constexpr int NB  = 256;     // batch
static constexpr int CAT = 1024;
static constexpr int HD  = 512;
static constexpr int VOC = 32000;
static constexpr int TT  = 8;
static constexpr int G4  = 4 * HD;  // 2048

// ---------------- device scratch (static: no allocation) ----------------
__device__ __half d_ctxin_hi[NB * CAT];
__device__ __half d_ctxin_lo[NB * CAT];
__device__ __half d_wm_hi[HD * CAT];
__device__ __half d_wm_lo[HD * CAT];
__device__ __half d_wih_hi[G4 * HD];   // gate-interleaved rows
__device__ __half d_wih_lo[G4 * HD];   // gate-interleaved rows
__device__ __half d_whhp[G4 * HD];     // gate-interleaved rows
__device__ __half d_wo16[VOC * HD];
__device__ float  d_bihp[G4];          // permuted b_ih
__device__ float  d_bhhp[G4];          // permuted b_hh
__device__ float  d_ctx32[NB * HD];
__device__ __half d_ctx_hi[NB * HD];
__device__ __half d_ctx_lo[NB * HD];
__device__ float  d_xproj[NB * G4];    // gate-interleaved cols
__device__ float  d_cst[NB * HD];
__device__ __half d_h_hi[NB * HD];
__device__ __half d_h_lo[NB * HD];
__device__ __half d_hall[NB * TT * HD];

// ---------------- PTX helpers ----------------
DI uint32_t smem_u32(const void* p) {
    uint32_t a;
    asm("{ .reg .u64 t; cvta.to.shared.u64 t, %1; cvt.u32.u64 %0, t; }"
        : "=r"(a) : "l"(p));
    return a;
}
DI void cp_async16(uint32_t dst, const void* src) {
    asm volatile("cp.async.cg.shared.global [%0], [%1], 16;"
                 :: "r"(dst), "l"(src) : "memory");
}
DI void cp_commit() { asm volatile("cp.async.commit_group;" ::: "memory"); }
template <int N>
DI void cp_wait() { asm volatile("cp.async.wait_group %0;" :: "n"(N) : "memory"); }

DI void ldsm_x4(uint32_t (&d)[4], uint32_t addr) {
    asm volatile("ldmatrix.sync.aligned.m8n8.x4.shared.b16 {%0,%1,%2,%3}, [%4];"
                 : "=r"(d[0]), "=r"(d[1]), "=r"(d[2]), "=r"(d[3]) : "r"(addr));
}
DI void mma16816(float (&c)[4], const uint32_t (&a)[4], uint32_t b0, uint32_t b1) {
    asm volatile(
        "mma.sync.aligned.m16n8k16.row.col.f32.f16.f16.f32 "
        "{%0,%1,%2,%3}, {%4,%5,%6,%7}, {%8,%9}, {%0,%1,%2,%3};"
        : "+f"(c[0]), "+f"(c[1]), "+f"(c[2]), "+f"(c[3])
        : "r"(a[0]), "r"(a[1]), "r"(a[2]), "r"(a[3]), "r"(b0), "r"(b1));
}

DI void split1(float v, __half& hi, __half& lo) {
    __half h = __float2half_rn(v);
    hi = h;
    lo = __float2half_rn(v - __half2float(h));
}
DI void split4(float4 v, __half2* hi2, __half2* lo2) {
    __half2 h01 = __floats2half2_rn(v.x, v.y);
    __half2 h23 = __floats2half2_rn(v.z, v.w);
    float2 f01 = __half22float2(h01);
    float2 f23 = __half22float2(h23);
    hi2[0] = h01; hi2[1] = h23;
    lo2[0] = __floats2half2_rn(v.x - f01.x, v.y - f01.y);
    lo2[1] = __floats2half2_rn(v.z - f23.x, v.w - f23.y);
}

// ---------------- merged conversion / permutation kernel ----------------
__global__ void k_prep(const float4* __restrict__ ctx, const float4* __restrict__ wm,
                       const float* __restrict__ wih, const float* __restrict__ whh,
                       const float4* __restrict__ wo,
                       const float* __restrict__ bih, const float* __restrict__ bhh) {
    constexpr int R0 = NB * CAT / 4;
    constexpr int R1 = R0 + HD * CAT / 4;
    constexpr int R2 = R1 + G4 * HD / 4;
    constexpr int R3 = R2 + G4 * HD / 4;
    constexpr int R4 = R3 + VOC * HD / 4;
    constexpr int HD4 = HD / 4;

    if (blockIdx.x == 0) {
        for (int p = threadIdx.x; p < G4; p += blockDim.x) {
            int j = p >> 2, q = p & 3;
            d_bihp[p] = bih[q * HD + j];
            d_bhhp[p] = bhh[q * HD + j];
        }
    }
    int stride = gridDim.x * blockDim.x;
    for (int u = blockIdx.x * blockDim.x + threadIdx.x; u < R4; u += stride) {
        if (u < R0) {
            split4(ctx[u], (__half2*)d_ctxin_hi + 2 * u, (__half2*)d_ctxin_lo + 2 * u);
        } else if (u < R1) {
            int v = u - R0;
            split4(wm[v], (__half2*)d_wm_hi + 2 * v, (__half2*)d_wm_lo + 2 * v);
        } else if (u < R2) {
            int v = u - R1;
            int p = v >> 7, c4 = v & (HD4 - 1);
            int j = p >> 2, q = p & 3;
            float4 w = *reinterpret_cast<const float4*>(wih + (size_t)(q * HD + j) * HD + c4 * 4);
            split4(w, (__half2*)d_wih_hi + 2 * v, (__half2*)d_wih_lo + 2 * v);
        } else if (u < R3) {
            int v = u - R2;
            int p = v >> 7, c4 = v & (HD4 - 1);
            int j = p >> 2, q = p & 3;
            float4 w = *reinterpret_cast<const float4*>(whh + (size_t)(q * HD + j) * HD + c4 * 4);
            __half2* o = (__half2*)d_whhp + 2 * v;
            o[0] = __floats2half2_rn(w.x, w.y);
            o[1] = __floats2half2_rn(w.z, w.w);
        } else {
            int v = u - R3;
            float4 w = wo[v];
            __half2* o = (__half2*)d_wo16 + 2 * v;
            o[0] = __floats2half2_rn(w.x, w.y);
            o[1] = __floats2half2_rn(w.z, w.w);
        }
    }
}

__global__ void k_split(const float* __restrict__ x, __half* __restrict__ hi,
                        __half* __restrict__ lo, int n) {
    int i = blockIdx.x * blockDim.x + threadIdx.x;
    if (i < n) split1(x[i], hi[i], lo[i]);
}

// ---------------- big HMMA GEMM: 128x128 tile, 256 thr, 3-stage pipeline ----
template <int NPASS>
__global__ void __launch_bounds__(256, 2)
k_gemm(float* __restrict__ C, int ldc,
       const __half* __restrict__ A0, const __half* __restrict__ A1,
       const __half* __restrict__ A2,
       const __half* __restrict__ B0, const __half* __restrict__ B1,
       const __half* __restrict__ B2,
       const float* __restrict__ bias, int K) {
    extern __shared__ char smem[];
    constexpr int TILE_B = 128 * 128;
    constexpr int STG    = 2 * TILE_B;

    const uint32_t sb = smem_u32(smem);
    const int tid    = threadIdx.x;
    const int lane   = tid & 31;
    const int wid    = tid >> 5;
    const int warp_m = wid & 3;
    const int warp_n = wid >> 2;

    const __half* Ap[3] = {A0, A1, A2};
    const __half* Bp[3] = {B0, B1, B2};

    const int mBase = blockIdx.y * 128;
    const int nBase = blockIdx.x * 128;
    const int kch   = K >> 6;
    const int total = NPASS * kch;

    const int ldr = tid >> 3;
    const int ldg = tid & 7;

    auto load_chunk = [&](int ch) {
        const int st   = ch % 3;
        const int pass = ch / kch;
        const int kc   = ch - pass * kch;
        const __half* Ag = Ap[pass] + (size_t)mBase * K + kc * 64;
        const __half* Bg = Bp[pass] + (size_t)nBase * K + kc * 64;
        const uint32_t a_u = sb + st * STG;
        const uint32_t b_u = a_u + TILE_B;
#pragma unroll
        for (int it = 0; it < 4; ++it) {
            int r = ldr + it * 32;
            uint32_t off = (uint32_t)(r * 128 + (ldg * 16 ^ ((r & 7) << 4)));
            cp_async16(a_u + off, Ag + (size_t)r * K + ldg * 8);
            cp_async16(b_u + off, Bg + (size_t)r * K + ldg * 8);
        }
        cp_commit();
    };

    float acc[2][8][4];
#pragma unroll
    for (int mi = 0; mi < 2; ++mi)
#pragma unroll
        for (int ni = 0; ni < 8; ++ni)
#pragma unroll
            for (int q = 0; q < 4; ++q) acc[mi][ni][q] = 0.f;

    int arow[2], brow[4];
#pragma unroll
    for (int mi = 0; mi < 2; ++mi)
        arow[mi] = warp_m * 32 + mi * 16 + (lane & 7) + ((lane >> 3) & 1) * 8;
#pragma unroll
    for (int nq = 0; nq < 4; ++nq)
        brow[nq] = warp_n * 64 + nq * 16 + (lane & 7) + (lane >> 4) * 8;
    const int akb = (lane >> 4) * 16;
    const int bkb = ((lane >> 3) & 1) * 16;

    load_chunk(0);
    load_chunk(1);

    for (int ch = 0; ch < total; ++ch) {
        if (ch + 1 < total) cp_wait<1>(); else cp_wait<0>();
        __syncthreads();                         // data(ch) visible; compute(ch-1) done
        if (ch + 2 < total) load_chunk(ch + 2);  // overwrites buf (ch-1)%3 — safe

        const uint32_t a_u = sb + (ch % 3) * STG;
        const uint32_t b_u = a_u + TILE_B;
#pragma unroll
        for (int ks = 0; ks < 4; ++ks) {
            uint32_t aF[2][4];
#pragma unroll
            for (int mi = 0; mi < 2; ++mi) {
                int r = arow[mi], kb = ks * 32 + akb;
                ldsm_x4(aF[mi], a_u + r * 128 + (kb ^ ((r & 7) << 4)));
            }
            uint32_t bF[4][4];
#pragma unroll
            for (int nq = 0; nq < 4; ++nq) {
                int r = brow[nq], kb = ks * 32 + bkb;
                ldsm_x4(bF[nq], b_u + r * 128 + (kb ^ ((r & 7) << 4)));
            }
#pragma unroll
            for (int mi = 0; mi < 2; ++mi)
#pragma unroll
                for (int ni = 0; ni < 8; ++ni)
                    mma16816(acc[mi][ni], aF[mi],
                             bF[ni >> 1][(ni & 1) * 2], bF[ni >> 1][(ni & 1) * 2 + 1]);
        }
    }

    const int m0 = mBase + warp_m * 32;
    const int n0 = nBase + warp_n * 64;
#pragma unroll
    for (int ni = 0; ni < 8; ++ni) {
        int col = n0 + ni * 8 + 2 * (lane & 3);
        float2 bv = *reinterpret_cast<const float2*>(bias + col);
#pragma unroll
        for (int mi = 0; mi < 2; ++mi) {
            int row = m0 + mi * 16 + (lane >> 2);
            float2 v0 = {acc[mi][ni][0] + bv.x, acc[mi][ni][1] + bv.y};
            float2 v1 = {acc[mi][ni][2] + bv.x, acc[mi][ni][3] + bv.y};
            *reinterpret_cast<float2*>(C + (size_t)row * ldc + col) = v0;
            *reinterpret_cast<float2*>(C + (size_t)(row + 8) * ldc + col) = v1;
        }
    }
}

// ---------------- 64x64 HMMA GEMM, 128 thr, 3-stage; MODE 0 = C+bias store,
// MODE 1 = fused LSTM cell epilogue (gate-interleaved columns) ----------------
template <int NPASS, int MODE>
__global__ void __launch_bounds__(128)
k_g64(float* __restrict__ C, int ldc,
      const __half* __restrict__ A0, const __half* __restrict__ A1,
      const __half* __restrict__ A2,
      const __half* __restrict__ B0, const __half* __restrict__ B1,
      const __half* __restrict__ B2,
      const float* __restrict__ bias, int K,
      const float* __restrict__ xproj, const float* __restrict__ bhhp,
      float* __restrict__ cst, __half* __restrict__ hhi, __half* __restrict__ hlo,
      __half* __restrict__ hall, int t) {
    extern __shared__ char smem[];
    constexpr int TILE_B = 64 * 128;   // 8 KB
    constexpr int STG    = 2 * TILE_B;

    const int tid    = threadIdx.x;
    const int lane   = tid & 31;
    const int wid    = tid >> 5;
    const int warp_m = wid & 1;
    const int warp_n = wid >> 1;

    const int mBase = blockIdx.y * 64;
    const int nBase = blockIdx.x * 64;

    float acc[2][4][4];
#pragma unroll
    for (int mi = 0; mi < 2; ++mi)
#pragma unroll
        for (int ni = 0; ni < 4; ++ni)
#pragma unroll
            for (int q = 0; q < 4; ++q) acc[mi][ni][q] = 0.f;

    if (NPASS > 0) {
        const uint32_t sb = smem_u32(smem);
        const __half* Ap[3] = {A0, A1, A2};
        const __half* Bp[3] = {B0, B1, B2};
        const int kch   = K >> 6;
        const int total = NPASS * kch;

        const int ldr = tid >> 3;   // 0..15
        const int ldg = tid & 7;

        auto load_chunk = [&](int ch) {
            const int st   = ch % 3;
            const int pass = ch / kch;
            const int kc   = ch - pass * kch;
            const __half* Ag = Ap[pass] + (size_t)mBase * K + kc * 64;
            const __half* Bg = Bp[pass] + (size_t)nBase * K + kc * 64;
            const uint32_t a_u = sb + st * STG;
            const uint32_t b_u = a_u + TILE_B;
#pragma unroll
            for (int it = 0; it < 4; ++it) {
                int r = ldr + it * 16;
                uint32_t off = (uint32_t)(r * 128 + (ldg * 16 ^ ((r & 7) << 4)));
                cp_async16(a_u + off, Ag + (size_t)r * K + ldg * 8);
                cp_async16(b_u + off, Bg + (size_t)r * K + ldg * 8);
            }
            cp_commit();
        };

        int arow[2], brow[2];
#pragma unroll
        for (int mi = 0; mi < 2; ++mi)
            arow[mi] = warp_m * 32 + mi * 16 + (lane & 7) + ((lane >> 3) & 1) * 8;
#pragma unroll
        for (int nq = 0; nq < 2; ++nq)
            brow[nq] = warp_n * 32 + nq * 16 + (lane & 7) + (lane >> 4) * 8;
        const int akb = (lane >> 4) * 16;
        const int bkb = ((lane >> 3) & 1) * 16;

        load_chunk(0);
        load_chunk(1);
        for (int ch = 0; ch < total; ++ch) {
            if (ch + 1 < total) cp_wait<1>(); else cp_wait<0>();
            __syncthreads();
            if (ch + 2 < total) load_chunk(ch + 2);

            const uint32_t a_u = sb + (ch % 3) * STG;
            const uint32_t b_u = a_u + TILE_B;
#pragma unroll
            for (int ks = 0; ks < 4; ++ks) {
                uint32_t aF[2][4];
#pragma unroll
                for (int mi = 0; mi < 2; ++mi) {
                    int r = arow[mi], kb = ks * 32 + akb;
                    ldsm_x4(aF[mi], a_u + r * 128 + (kb ^ ((r & 7) << 4)));
                }
                uint32_t bF[2][4];
#pragma unroll
                for (int nq = 0; nq < 2; ++nq) {
                    int r = brow[nq], kb = ks * 32 + bkb;
                    ldsm_x4(bF[nq], b_u + r * 128 + (kb ^ ((r & 7) << 4)));
                }
#pragma unroll
                for (int mi = 0; mi < 2; ++mi)
#pragma unroll
                    for (int ni = 0; ni < 4; ++ni)
                        mma16816(acc[mi][ni], aF[mi],
                                 bF[ni >> 1][(ni & 1) * 2], bF[ni >> 1][(ni & 1) * 2 + 1]);
            }
        }
    }

    if (MODE == 0) {
        // plain store: C = acc + bias
        const int m0 = mBase + warp_m * 32;
        const int n0 = nBase + warp_n * 32;
#pragma unroll
        for (int ni = 0; ni < 4; ++ni) {
            int col = n0 + ni * 8 + 2 * (lane & 3);
            float2 bv = *reinterpret_cast<const float2*>(bias + col);
#pragma unroll
            for (int mi = 0; mi < 2; ++mi) {
                int row = m0 + mi * 16 + (lane >> 2);
                float2 v0 = {acc[mi][ni][0] + bv.x, acc[mi][ni][1] + bv.y};
                float2 v1 = {acc[mi][ni][2] + bv.x, acc[mi][ni][3] + bv.y};
                *reinterpret_cast<float2*>(C + (size_t)row * ldc + col) = v0;
                *reinterpret_cast<float2*>(C + (size_t)(row + 8) * ldc + col) = v1;
            }
        }
    } else {
        // LSTM cell epilogue (gate-interleaved cols)
        const int m0  = mBase + warp_m * 32;
        const int n0g = nBase + warp_n * 32;
        const int a   = lane & 3;
        const int rb  = lane >> 2;
#pragma unroll
        for (int ni = 0; ni < 4; ++ni) {
            int col = n0g + ni * 8 + 2 * a;
            float2 bb = *reinterpret_cast<const float2*>(bhhp + col);
#pragma unroll
            for (int mi = 0; mi < 2; ++mi) {
#pragma unroll
                for (int hq = 0; hq < 2; ++hq) {
                    int row = m0 + mi * 16 + rb + hq * 8;
                    float2 xp = *reinterpret_cast<const float2*>(xproj + (size_t)row * G4 + col);
                    float g0 = acc[mi][ni][hq * 2 + 0] + xp.x + bb.x;
                    float g1 = acc[mi][ni][hq * 2 + 1] + xp.y + bb.y;
                    float o0 = __shfl_xor_sync(0xFFFFFFFFu, g0, 1);
                    float o1 = __shfl_xor_sync(0xFFFFFFFFu, g1, 1);
                    if ((a & 1) == 0) {
                        float si = 1.f / (1.f + expf(-g0));
                        float sf = 1.f / (1.f + expf(-g1));
                        float tg = tanhf(o0);
                        float so = 1.f / (1.f + expf(-o1));
                        int j = (n0g >> 2) + 2 * ni + (a >> 1);
                        float cp = (NPASS == 0) ? 0.f : cst[(size_t)row * HD + j];
                        float cn = sf * cp + si * tg;
                        cst[(size_t)row * HD + j] = cn;
                        float h = so * tanhf(cn);
                        __half hh = __float2half_rn(h);
                        hhi[(size_t)row * HD + j] = hh;
                        hlo[(size_t)row * HD + j] = __float2half_rn(h - __half2float(hh));
                        hall[((size_t)row * TT + t) * HD + j] = hh;
                    }
                }
            }
        }
    }
}

// ---------------- host orchestration ----------------
extern "C" void kernel_launch(void* const* d_in, const int* in_sizes, int n_in,
                              void* d_out, int out_size) {
    const float* context = (const float*)d_in[0];
    const float* W_merge = (const float*)d_in[1];
    const float* b_merge = (const float*)d_in[2];
    const float* W_ih    = (const float*)d_in[3];
    const float* W_hh    = (const float*)d_in[4];
    const float* b_ih    = (const float*)d_in[5];
    const float* b_hh    = (const float*)d_in[6];
    const float* W_out   = (const float*)d_in[7];
    const float* b_out   = (const float*)d_in[8];
    float* out = (float*)d_out;

    __half *ctxin_hi, *ctxin_lo, *wm_hi, *wm_lo, *wih_hi, *wih_lo, *whhp, *wo16;
    __half *ctx_hi, *ctx_lo, *h_hi, *h_lo, *hall;
    float *ctx32, *xproj, *cbuf, *bihp, *bhhp;
    cudaGetSymbolAddress((void**)&ctxin_hi, d_ctxin_hi);
    cudaGetSymbolAddress((void**)&ctxin_lo, d_ctxin_lo);
    cudaGetSymbolAddress((void**)&wm_hi, d_wm_hi);
    cudaGetSymbolAddress((void**)&wm_lo, d_wm_lo);
    cudaGetSymbolAddress((void**)&wih_hi, d_wih_hi);
    cudaGetSymbolAddress((void**)&wih_lo, d_wih_lo);
    cudaGetSymbolAddress((void**)&whhp, d_whhp);
    cudaGetSymbolAddress((void**)&wo16, d_wo16);
    cudaGetSymbolAddress((void**)&bihp, d_bihp);
    cudaGetSymbolAddress((void**)&bhhp, d_bhhp);
    cudaGetSymbolAddress((void**)&ctx32, d_ctx32);
    cudaGetSymbolAddress((void**)&ctx_hi, d_ctx_hi);
    cudaGetSymbolAddress((void**)&ctx_lo, d_ctx_lo);
    cudaGetSymbolAddress((void**)&xproj, d_xproj);
    cudaGetSymbolAddress((void**)&cbuf, d_cst);
    cudaGetSymbolAddress((void**)&h_hi, d_h_hi);
    cudaGetSymbolAddress((void**)&h_lo, d_h_lo);
    cudaGetSymbolAddress((void**)&hall, d_hall);

    const int SMEM128 = 3 * 2 * 128 * 128;  // 98304
    const int SMEM64  = 3 * 2 * 64 * 128;   // 49152
    cudaFuncSetAttribute(k_gemm<1>, cudaFuncAttributeMaxDynamicSharedMemorySize, SMEM128);
    cudaFuncSetAttribute(k_g64<3, 0>, cudaFuncAttributeMaxDynamicSharedMemorySize, SMEM64);
    cudaFuncSetAttribute(k_g64<2, 1>, cudaFuncAttributeMaxDynamicSharedMemorySize, SMEM64);

    // one merged conversion + permutation kernel
    k_prep<<<2048, 256>>>((const float4*)context, (const float4*)W_merge,
                          W_ih, W_hh, (const float4*)W_out, b_ih, b_hh);

    // GEMM1: ctx = context @ Wm^T + b_merge   (3-pass split-fp16 ~ fp32)
    {
        dim3 g(HD / 64, NB / 64);  // (8,4) = 32 CTAs
        k_g64<3, 0><<<g, 128, SMEM64>>>(ctx32, HD,
            ctxin_hi, ctxin_lo, ctxin_hi,
            wm_hi, wm_hi, wm_lo,
            b_merge, CAT,
            nullptr, nullptr, nullptr, nullptr, nullptr, nullptr, 0);
    }
    k_split<<<(NB * HD + 255) / 256, 256>>>(ctx32, ctx_hi, ctx_lo, NB * HD);
    // GEMM2: x_proj(perm) = ctx @ Wih_p^T + b_ih_p   (3-pass)
    {
        dim3 g(G4 / 64, NB / 64);  // (32,4) = 128 CTAs
        k_g64<3, 0><<<g, 128, SMEM64>>>(xproj, G4,
            ctx_hi, ctx_lo, ctx_hi,
            wih_hi, wih_hi, wih_lo,
            bihp, HD,
            nullptr, nullptr, nullptr, nullptr, nullptr, nullptr, 0);
    }
    // LSTM recurrence: one fused kernel per step
    {
        dim3 g(G4 / 64, NB / 64);  // (32,4) = 128 CTAs
        k_g64<0, 1><<<g, 128, 0>>>(nullptr, 0,
            h_hi, h_lo, h_hi, whhp, whhp, whhp, nullptr, HD,
            xproj, bhhp, cbuf, h_hi, h_lo, hall, 0);
        for (int t = 1; t < TT; ++t)
            k_g64<2, 1><<<g, 128, SMEM64>>>(nullptr, 0,
                h_hi, h_lo, h_hi, whhp, whhp, whhp, nullptr, HD,
                xproj, bhhp, cbuf, h_hi, h_lo, hall, t);
    }
    // Big GEMM: out[2048,32000] = H_all @ Wo^T + b_out
    {
        dim3 g(VOC / 128, (NB * TT) / 128);  // (250,16)
        k_gemm<1><<<g, 256, SMEM128>>>(out, VOC,
            hall, hall, hall,
            wo16, wo16, wo16,
            b_out, HD);
    }
}

// round 5
// speedup vs baseline: 1.2048x; 1.0146x over previous
#include <cuda_runtime.h>
#include <cuda_fp16.h>
#include <cstdint>
#include <cstddef>

#define DI __device__ __forceinline__

static constexpr int NB  = 256;     // batch
static constexpr int CAT = 1024;
static constexpr int HD  = 512;
static constexpr int VOC = 32000;
static constexpr int TT  = 8;
static constexpr int G4  = 4 * HD;  // 2048
static constexpr int REC_CTAS = (G4 / 64) * (NB / 64);  // 128

// ---------------- device scratch (static: no allocation) ----------------
__device__ __half d_ctxin_hi[NB * CAT];
__device__ __half d_ctxin_lo[NB * CAT];
__device__ __half d_wm_hi[HD * CAT];
__device__ __half d_wm_lo[HD * CAT];
__device__ __half d_wih_hi[G4 * HD];   // gate-interleaved rows
__device__ __half d_wih_lo[G4 * HD];   // gate-interleaved rows
__device__ __half d_whhp[G4 * HD];     // gate-interleaved rows
__device__ __half d_wo16[VOC * HD];
__device__ float  d_bihp[G4];          // permuted b_ih
__device__ float  d_bhhp[G4];          // permuted b_hh
__device__ float  d_ctx32[NB * HD];
__device__ __half d_ctx_hi[NB * HD];
__device__ __half d_ctx_lo[NB * HD];
__device__ float  d_xproj[NB * G4];    // gate-interleaved cols
__device__ float  d_cst[NB * HD];
__device__ __half d_h_hi[2][NB * HD];  // double-buffered across steps
__device__ __half d_h_lo[2][NB * HD];
__device__ __half d_hall[NB * TT * HD];
__device__ unsigned d_bar_cnt = 0;
__device__ unsigned d_bar_gen = 0;

// ---------------- PTX helpers ----------------
DI uint32_t smem_u32(const void* p) {
    uint32_t a;
    asm("{ .reg .u64 t; cvta.to.shared.u64 t, %1; cvt.u32.u64 %0, t; }"
        : "=r"(a) : "l"(p));
    return a;
}
DI void cp_async16(uint32_t dst, const void* src) {
    asm volatile("cp.async.cg.shared.global [%0], [%1], 16;"
                 :: "r"(dst), "l"(src) : "memory");
}
DI void cp_commit() { asm volatile("cp.async.commit_group;" ::: "memory"); }
template <int N>
DI void cp_wait() { asm volatile("cp.async.wait_group %0;" :: "n"(N) : "memory"); }

DI void ldsm_x4(uint32_t (&d)[4], uint32_t addr) {
    asm volatile("ldmatrix.sync.aligned.m8n8.x4.shared.b16 {%0,%1,%2,%3}, [%4];"
                 : "=r"(d[0]), "=r"(d[1]), "=r"(d[2]), "=r"(d[3]) : "r"(addr));
}
DI void mma16816(float (&c)[4], const uint32_t (&a)[4], uint32_t b0, uint32_t b1) {
    asm volatile(
        "mma.sync.aligned.m16n8k16.row.col.f32.f16.f16.f32 "
        "{%0,%1,%2,%3}, {%4,%5,%6,%7}, {%8,%9}, {%0,%1,%2,%3};"
        : "+f"(c[0]), "+f"(c[1]), "+f"(c[2]), "+f"(c[3])
        : "r"(a[0]), "r"(a[1]), "r"(a[2]), "r"(a[3]), "r"(b0), "r"(b1));
}

DI void split1(float v, __half& hi, __half& lo) {
    __half h = __float2half_rn(v);
    hi = h;
    lo = __float2half_rn(v - __half2float(h));
}
DI void split4(float4 v, __half2* hi2, __half2* lo2) {
    __half2 h01 = __floats2half2_rn(v.x, v.y);
    __half2 h23 = __floats2half2_rn(v.z, v.w);
    float2 f01 = __half22float2(h01);
    float2 f23 = __half22float2(h23);
    hi2[0] = h01; hi2[1] = h23;
    lo2[0] = __floats2half2_rn(v.x - f01.x, v.y - f01.y);
    lo2[1] = __floats2half2_rn(v.z - f23.x, v.w - f23.y);
}

// device-wide sense barrier (all REC_CTAS CTAs co-resident)
DI void grid_barrier() {
    __syncthreads();
    if (threadIdx.x == 0) {
        __threadfence();
        unsigned g;
        asm volatile("ld.acquire.gpu.global.u32 %0, [%1];"
                     : "=r"(g) : "l"(&d_bar_gen));
        unsigned v = atomicAdd(&d_bar_cnt, 1u);
        if (v == REC_CTAS - 1) {
            d_bar_cnt = 0;
            asm volatile("red.release.gpu.global.add.u32 [%0], 1;"
                         :: "l"(&d_bar_gen) : "memory");
        } else {
            unsigned cur;
            do {
                asm volatile("ld.acquire.gpu.global.u32 %0, [%1];"
                             : "=r"(cur) : "l"(&d_bar_gen));
            } while (cur == g);
        }
    }
    __syncthreads();
}

// ---------------- merged conversion / permutation kernel ----------------
__global__ void k_prep(const float4* __restrict__ ctx, const float4* __restrict__ wm,
                       const float* __restrict__ wih, const float* __restrict__ whh,
                       const float4* __restrict__ wo,
                       const float* __restrict__ bih, const float* __restrict__ bhh) {
    constexpr int R0 = NB * CAT / 4;
    constexpr int R1 = R0 + HD * CAT / 4;
    constexpr int R2 = R1 + G4 * HD / 4;
    constexpr int R3 = R2 + G4 * HD / 4;
    constexpr int R4 = R3 + VOC * HD / 4;
    constexpr int HD4 = HD / 4;

    if (blockIdx.x == 0) {
        for (int p = threadIdx.x; p < G4; p += blockDim.x) {
            int j = p >> 2, q = p & 3;
            d_bihp[p] = bih[q * HD + j];
            d_bhhp[p] = bhh[q * HD + j];
        }
    }
    int stride = gridDim.x * blockDim.x;
    for (int u = blockIdx.x * blockDim.x + threadIdx.x; u < R4; u += stride) {
        if (u < R0) {
            split4(ctx[u], (__half2*)d_ctxin_hi + 2 * u, (__half2*)d_ctxin_lo + 2 * u);
        } else if (u < R1) {
            int v = u - R0;
            split4(wm[v], (__half2*)d_wm_hi + 2 * v, (__half2*)d_wm_lo + 2 * v);
        } else if (u < R2) {
            int v = u - R1;
            int p = v >> 7, c4 = v & (HD4 - 1);
            int j = p >> 2, q = p & 3;
            float4 w = *reinterpret_cast<const float4*>(wih + (size_t)(q * HD + j) * HD + c4 * 4);
            split4(w, (__half2*)d_wih_hi + 2 * v, (__half2*)d_wih_lo + 2 * v);
        } else if (u < R3) {
            int v = u - R2;
            int p = v >> 7, c4 = v & (HD4 - 1);
            int j = p >> 2, q = p & 3;
            float4 w = *reinterpret_cast<const float4*>(whh + (size_t)(q * HD + j) * HD + c4 * 4);
            __half2* o = (__half2*)d_whhp + 2 * v;
            o[0] = __floats2half2_rn(w.x, w.y);
            o[1] = __floats2half2_rn(w.z, w.w);
        } else {
            int v = u - R3;
            float4 w = wo[v];
            __half2* o = (__half2*)d_wo16 + 2 * v;
            o[0] = __floats2half2_rn(w.x, w.y);
            o[1] = __floats2half2_rn(w.z, w.w);
        }
    }
}

__global__ void k_split(const float* __restrict__ x, __half* __restrict__ hi,
                        __half* __restrict__ lo, int n) {
    int i = blockIdx.x * blockDim.x + threadIdx.x;
    if (i < n) split1(x[i], hi[i], lo[i]);
}

// ---------------- big HMMA GEMM: 128x128 tile, 256 thr, 3-stage pipeline ----
template <int NPASS>
__global__ void __launch_bounds__(256, 2)
k_gemm(float* __restrict__ C, int ldc,
       const __half* __restrict__ A0, const __half* __restrict__ A1,
       const __half* __restrict__ A2,
       const __half* __restrict__ B0, const __half* __restrict__ B1,
       const __half* __restrict__ B2,
       const float* __restrict__ bias, int K) {
    extern __shared__ char smem[];
    constexpr int TILE_B = 128 * 128;
    constexpr int STG    = 2 * TILE_B;

    const uint32_t sb = smem_u32(smem);
    const int tid    = threadIdx.x;
    const int lane   = tid & 31;
    const int wid    = tid >> 5;
    const int warp_m = wid & 3;
    const int warp_n = wid >> 2;

    const __half* Ap[3] = {A0, A1, A2};
    const __half* Bp[3] = {B0, B1, B2};

    const int mBase = blockIdx.y * 128;
    const int nBase = blockIdx.x * 128;
    const int kch   = K >> 6;
    const int total = NPASS * kch;

    const int ldr = tid >> 3;
    const int ldg = tid & 7;

    auto load_chunk = [&](int ch) {
        const int st   = ch % 3;
        const int pass = ch / kch;
        const int kc   = ch - pass * kch;
        const __half* Ag = Ap[pass] + (size_t)mBase * K + kc * 64;
        const __half* Bg = Bp[pass] + (size_t)nBase * K + kc * 64;
        const uint32_t a_u = sb + st * STG;
        const uint32_t b_u = a_u + TILE_B;
#pragma unroll
        for (int it = 0; it < 4; ++it) {
            int r = ldr + it * 32;
            uint32_t off = (uint32_t)(r * 128 + (ldg * 16 ^ ((r & 7) << 4)));
            cp_async16(a_u + off, Ag + (size_t)r * K + ldg * 8);
            cp_async16(b_u + off, Bg + (size_t)r * K + ldg * 8);
        }
        cp_commit();
    };

    float acc[2][8][4];
#pragma unroll
    for (int mi = 0; mi < 2; ++mi)
#pragma unroll
        for (int ni = 0; ni < 8; ++ni)
#pragma unroll
            for (int q = 0; q < 4; ++q) acc[mi][ni][q] = 0.f;

    int arow[2], brow[4];
#pragma unroll
    for (int mi = 0; mi < 2; ++mi)
        arow[mi] = warp_m * 32 + mi * 16 + (lane & 7) + ((lane >> 3) & 1) * 8;
#pragma unroll
    for (int nq = 0; nq < 4; ++nq)
        brow[nq] = warp_n * 64 + nq * 16 + (lane & 7) + (lane >> 4) * 8;
    const int akb = (lane >> 4) * 16;
    const int bkb = ((lane >> 3) & 1) * 16;

    load_chunk(0);
    load_chunk(1);

    for (int ch = 0; ch < total; ++ch) {
        if (ch + 1 < total) cp_wait<1>(); else cp_wait<0>();
        __syncthreads();
        if (ch + 2 < total) load_chunk(ch + 2);

        const uint32_t a_u = sb + (ch % 3) * STG;
        const uint32_t b_u = a_u + TILE_B;
#pragma unroll
        for (int ks = 0; ks < 4; ++ks) {
            uint32_t aF[2][4];
#pragma unroll
            for (int mi = 0; mi < 2; ++mi) {
                int r = arow[mi], kb = ks * 32 + akb;
                ldsm_x4(aF[mi], a_u + r * 128 + (kb ^ ((r & 7) << 4)));
            }
            uint32_t bF[4][4];
#pragma unroll
            for (int nq = 0; nq < 4; ++nq) {
                int r = brow[nq], kb = ks * 32 + bkb;
                ldsm_x4(bF[nq], b_u + r * 128 + (kb ^ ((r & 7) << 4)));
            }
#pragma unroll
            for (int mi = 0; mi < 2; ++mi)
#pragma unroll
                for (int ni = 0; ni < 8; ++ni)
                    mma16816(acc[mi][ni], aF[mi],
                             bF[ni >> 1][(ni & 1) * 2], bF[ni >> 1][(ni & 1) * 2 + 1]);
        }
    }

    const int m0 = mBase + warp_m * 32;
    const int n0 = nBase + warp_n * 64;
#pragma unroll
    for (int ni = 0; ni < 8; ++ni) {
        int col = n0 + ni * 8 + 2 * (lane & 3);
        float2 bv = *reinterpret_cast<const float2*>(bias + col);
#pragma unroll
        for (int mi = 0; mi < 2; ++mi) {
            int row = m0 + mi * 16 + (lane >> 2);
            float2 v0 = {acc[mi][ni][0] + bv.x, acc[mi][ni][1] + bv.y};
            float2 v1 = {acc[mi][ni][2] + bv.x, acc[mi][ni][3] + bv.y};
            *reinterpret_cast<float2*>(C + (size_t)row * ldc + col) = v0;
            *reinterpret_cast<float2*>(C + (size_t)(row + 8) * ldc + col) = v1;
        }
    }
}

// ---------------- 64x64 HMMA GEMM, 128 thr, 3-stage, C = acc + bias ---------
template <int NPASS>
__global__ void __launch_bounds__(128)
k_g64(float* __restrict__ C, int ldc,
      const __half* __restrict__ A0, const __half* __restrict__ A1,
      const __half* __restrict__ A2,
      const __half* __restrict__ B0, const __half* __restrict__ B1,
      const __half* __restrict__ B2,
      const float* __restrict__ bias, int K) {
    extern __shared__ char smem[];
    constexpr int TILE_B = 64 * 128;
    constexpr int STG    = 2 * TILE_B;

    const uint32_t sb = smem_u32(smem);
    const int tid    = threadIdx.x;
    const int lane   = tid & 31;
    const int wid    = tid >> 5;
    const int warp_m = wid & 1;
    const int warp_n = wid >> 1;

    const int mBase = blockIdx.y * 64;
    const int nBase = blockIdx.x * 64;

    const __half* Ap[3] = {A0, A1, A2};
    const __half* Bp[3] = {B0, B1, B2};
    const int kch   = K >> 6;
    const int total = NPASS * kch;

    const int ldr = tid >> 3;
    const int ldg = tid & 7;

    auto load_chunk = [&](int ch) {
        const int st   = ch % 3;
        const int pass = ch / kch;
        const int kc   = ch - pass * kch;
        const __half* Ag = Ap[pass] + (size_t)mBase * K + kc * 64;
        const __half* Bg = Bp[pass] + (size_t)nBase * K + kc * 64;
        const uint32_t a_u = sb + st * STG;
        const uint32_t b_u = a_u + TILE_B;
#pragma unroll
        for (int it = 0; it < 4; ++it) {
            int r = ldr + it * 16;
            uint32_t off = (uint32_t)(r * 128 + (ldg * 16 ^ ((r & 7) << 4)));
            cp_async16(a_u + off, Ag + (size_t)r * K + ldg * 8);
            cp_async16(b_u + off, Bg + (size_t)r * K + ldg * 8);
        }
        cp_commit();
    };

    float acc[2][4][4];
#pragma unroll
    for (int mi = 0; mi < 2; ++mi)
#pragma unroll
        for (int ni = 0; ni < 4; ++ni)
#pragma unroll
            for (int q = 0; q < 4; ++q) acc[mi][ni][q] = 0.f;

    int arow[2], brow[2];
#pragma unroll
    for (int mi = 0; mi < 2; ++mi)
        arow[mi] = warp_m * 32 + mi * 16 + (lane & 7) + ((lane >> 3) & 1) * 8;
#pragma unroll
    for (int nq = 0; nq < 2; ++nq)
        brow[nq] = warp_n * 32 + nq * 16 + (lane & 7) + (lane >> 4) * 8;
    const int akb = (lane >> 4) * 16;
    const int bkb = ((lane >> 3) & 1) * 16;

    load_chunk(0);
    load_chunk(1);
    for (int ch = 0; ch < total; ++ch) {
        if (ch + 1 < total) cp_wait<1>(); else cp_wait<0>();
        __syncthreads();
        if (ch + 2 < total) load_chunk(ch + 2);

        const uint32_t a_u = sb + (ch % 3) * STG;
        const uint32_t b_u = a_u + TILE_B;
#pragma unroll
        for (int ks = 0; ks < 4; ++ks) {
            uint32_t aF[2][4];
#pragma unroll
            for (int mi = 0; mi < 2; ++mi) {
                int r = arow[mi], kb = ks * 32 + akb;
                ldsm_x4(aF[mi], a_u + r * 128 + (kb ^ ((r & 7) << 4)));
            }
            uint32_t bF[2][4];
#pragma unroll
            for (int nq = 0; nq < 2; ++nq) {
                int r = brow[nq], kb = ks * 32 + bkb;
                ldsm_x4(bF[nq], b_u + r * 128 + (kb ^ ((r & 7) << 4)));
            }
#pragma unroll
            for (int mi = 0; mi < 2; ++mi)
#pragma unroll
                for (int ni = 0; ni < 4; ++ni)
                    mma16816(acc[mi][ni], aF[mi],
                             bF[ni >> 1][(ni & 1) * 2], bF[ni >> 1][(ni & 1) * 2 + 1]);
        }
    }

    const int m0 = mBase + warp_m * 32;
    const int n0 = nBase + warp_n * 32;
#pragma unroll
    for (int ni = 0; ni < 4; ++ni) {
        int col = n0 + ni * 8 + 2 * (lane & 3);
        float2 bv = *reinterpret_cast<const float2*>(bias + col);
#pragma unroll
        for (int mi = 0; mi < 2; ++mi) {
            int row = m0 + mi * 16 + (lane >> 2);
            float2 v0 = {acc[mi][ni][0] + bv.x, acc[mi][ni][1] + bv.y};
            float2 v1 = {acc[mi][ni][2] + bv.x, acc[mi][ni][3] + bv.y};
            *reinterpret_cast<float2*>(C + (size_t)row * ldc + col) = v0;
            *reinterpret_cast<float2*>(C + (size_t)(row + 8) * ldc + col) = v1;
        }
    }
}

// ---------------- persistent LSTM recurrence: all TT steps in one kernel ----
// Grid (G4/64, NB/64) = 128 CTAs, 128 threads. Per step: 64x64 gates GEMM
// (2-pass split-fp16 h @ Whh_p^T) + fused cell epilogue; device barrier
// between steps; h double-buffered (read t&1, write (t+1)&1).
__global__ void __launch_bounds__(128)
k_rec(const __half* __restrict__ Bw, const float* __restrict__ xproj,
      const float* __restrict__ bhhp, float* __restrict__ cst,
      __half* __restrict__ hall) {
    extern __shared__ char smem[];
    constexpr int TILE_B = 64 * 128;
    constexpr int STG    = 2 * TILE_B;

    const uint32_t sb = smem_u32(smem);
    const int tid    = threadIdx.x;
    const int lane   = tid & 31;
    const int wid    = tid >> 5;
    const int warp_m = wid & 1;
    const int warp_n = wid >> 1;

    const int mBase = blockIdx.y * 64;
    const int nBase = blockIdx.x * 64;

    const int ldr = tid >> 3;
    const int ldg = tid & 7;

    int arow[2], brow[2];
#pragma unroll
    for (int mi = 0; mi < 2; ++mi)
        arow[mi] = warp_m * 32 + mi * 16 + (lane & 7) + ((lane >> 3) & 1) * 8;
#pragma unroll
    for (int nq = 0; nq < 2; ++nq)
        brow[nq] = warp_n * 32 + nq * 16 + (lane & 7) + (lane >> 4) * 8;
    const int akb = (lane >> 4) * 16;
    const int bkb = ((lane >> 3) & 1) * 16;

    for (int t = 0; t < TT; ++t) {
        float acc[2][4][4];
#pragma unroll
        for (int mi = 0; mi < 2; ++mi)
#pragma unroll
            for (int ni = 0; ni < 4; ++ni)
#pragma unroll
                for (int q = 0; q < 4; ++q) acc[mi][ni][q] = 0.f;

        if (t > 0) {
            const int rd = t & 1;
            const __half* Ap[2] = {d_h_hi[rd], d_h_lo[rd]};
            const int total = 16;  // 2 passes x 8 chunks

            auto load_chunk = [&](int ch) {
                const int st   = ch % 3;
                const int pass = ch >> 3;
                const int kc   = ch & 7;
                const __half* Ag = Ap[pass] + (size_t)mBase * HD + kc * 64;
                const __half* Bg = Bw + (size_t)nBase * HD + kc * 64;
                const uint32_t a_u = sb + st * STG;
                const uint32_t b_u = a_u + TILE_B;
#pragma unroll
                for (int it = 0; it < 4; ++it) {
                    int r = ldr + it * 16;
                    uint32_t off = (uint32_t)(r * 128 + (ldg * 16 ^ ((r & 7) << 4)));
                    cp_async16(a_u + off, Ag + (size_t)r * HD + ldg * 8);
                    cp_async16(b_u + off, Bg + (size_t)r * HD + ldg * 8);
                }
                cp_commit();
            };

            load_chunk(0);
            load_chunk(1);
            for (int ch = 0; ch < total; ++ch) {
                if (ch + 1 < total) cp_wait<1>(); else cp_wait<0>();
                __syncthreads();
                if (ch + 2 < total) load_chunk(ch + 2);

                const uint32_t a_u = sb + (ch % 3) * STG;
                const uint32_t b_u = a_u + TILE_B;
#pragma unroll
                for (int ks = 0; ks < 4; ++ks) {
                    uint32_t aF[2][4];
#pragma unroll
                    for (int mi = 0; mi < 2; ++mi) {
                        int r = arow[mi], kb = ks * 32 + akb;
                        ldsm_x4(aF[mi], a_u + r * 128 + (kb ^ ((r & 7) << 4)));
                    }
                    uint32_t bF[2][4];
#pragma unroll
                    for (int nq = 0; nq < 2; ++nq) {
                        int r = brow[nq], kb = ks * 32 + bkb;
                        ldsm_x4(bF[nq], b_u + r * 128 + (kb ^ ((r & 7) << 4)));
                    }
#pragma unroll
                    for (int mi = 0; mi < 2; ++mi)
#pragma unroll
                        for (int ni = 0; ni < 4; ++ni)
                            mma16816(acc[mi][ni], aF[mi],
                                     bF[ni >> 1][(ni & 1) * 2], bF[ni >> 1][(ni & 1) * 2 + 1]);
                }
            }
        }

        // ---- cell epilogue: write h into buffer (t+1)&1 ----
        {
            const int wr = (t + 1) & 1;
            __half* hhi = d_h_hi[wr];
            __half* hlo = d_h_lo[wr];
            const int m0  = mBase + warp_m * 32;
            const int n0g = nBase + warp_n * 32;
            const int a   = lane & 3;
            const int rb  = lane >> 2;
#pragma unroll
            for (int ni = 0; ni < 4; ++ni) {
                int col = n0g + ni * 8 + 2 * a;
                float2 bb = *reinterpret_cast<const float2*>(bhhp + col);
#pragma unroll
                for (int mi = 0; mi < 2; ++mi) {
#pragma unroll
                    for (int hq = 0; hq < 2; ++hq) {
                        int row = m0 + mi * 16 + rb + hq * 8;
                        float2 xp = *reinterpret_cast<const float2*>(
                            xproj + (size_t)row * G4 + col);
                        float g0 = acc[mi][ni][hq * 2 + 0] + xp.x + bb.x;
                        float g1 = acc[mi][ni][hq * 2 + 1] + xp.y + bb.y;
                        float o0 = __shfl_xor_sync(0xFFFFFFFFu, g0, 1);
                        float o1 = __shfl_xor_sync(0xFFFFFFFFu, g1, 1);
                        if ((a & 1) == 0) {
                            float si = 1.f / (1.f + expf(-g0));
                            float sf = 1.f / (1.f + expf(-g1));
                            float tg = tanhf(o0);
                            float so = 1.f / (1.f + expf(-o1));
                            int j = (n0g >> 2) + 2 * ni + (a >> 1);
                            float cp = (t == 0) ? 0.f : cst[(size_t)row * HD + j];
                            float cn = sf * cp + si * tg;
                            cst[(size_t)row * HD + j] = cn;
                            float h = so * tanhf(cn);
                            __half hh = __float2half_rn(h);
                            hhi[(size_t)row * HD + j] = hh;
                            hlo[(size_t)row * HD + j] = __float2half_rn(h - __half2float(hh));
                            hall[((size_t)row * TT + t) * HD + j] = hh;
                        }
                    }
                }
            }
        }

        if (t + 1 < TT) grid_barrier();
    }
}

// ---------------- host orchestration ----------------
extern "C" void kernel_launch(void* const* d_in, const int* in_sizes, int n_in,
                              void* d_out, int out_size) {
    const float* context = (const float*)d_in[0];
    const float* W_merge = (const float*)d_in[1];
    const float* b_merge = (const float*)d_in[2];
    const float* W_ih    = (const float*)d_in[3];
    const float* W_hh    = (const float*)d_in[4];
    const float* b_ih    = (const float*)d_in[5];
    const float* b_hh    = (const float*)d_in[6];
    const float* W_out   = (const float*)d_in[7];
    const float* b_out   = (const float*)d_in[8];
    float* out = (float*)d_out;

    __half *ctxin_hi, *ctxin_lo, *wm_hi, *wm_lo, *wih_hi, *wih_lo, *whhp, *wo16;
    __half *ctx_hi, *ctx_lo, *hall;
    float *ctx32, *xproj, *cbuf, *bihp, *bhhp;
    cudaGetSymbolAddress((void**)&ctxin_hi, d_ctxin_hi);
    cudaGetSymbolAddress((void**)&ctxin_lo, d_ctxin_lo);
    cudaGetSymbolAddress((void**)&wm_hi, d_wm_hi);
    cudaGetSymbolAddress((void**)&wm_lo, d_wm_lo);
    cudaGetSymbolAddress((void**)&wih_hi, d_wih_hi);
    cudaGetSymbolAddress((void**)&wih_lo, d_wih_lo);
    cudaGetSymbolAddress((void**)&whhp, d_whhp);
    cudaGetSymbolAddress((void**)&wo16, d_wo16);
    cudaGetSymbolAddress((void**)&bihp, d_bihp);
    cudaGetSymbolAddress((void**)&bhhp, d_bhhp);
    cudaGetSymbolAddress((void**)&ctx32, d_ctx32);
    cudaGetSymbolAddress((void**)&ctx_hi, d_ctx_hi);
    cudaGetSymbolAddress((void**)&ctx_lo, d_ctx_lo);
    cudaGetSymbolAddress((void**)&xproj, d_xproj);
    cudaGetSymbolAddress((void**)&cbuf, d_cst);
    cudaGetSymbolAddress((void**)&hall, d_hall);

    const int SMEM128 = 3 * 2 * 128 * 128;  // 98304
    const int SMEM64  = 3 * 2 * 64 * 128;   // 49152
    cudaFuncSetAttribute(k_gemm<1>, cudaFuncAttributeMaxDynamicSharedMemorySize, SMEM128);
    cudaFuncSetAttribute(k_g64<3>, cudaFuncAttributeMaxDynamicSharedMemorySize, SMEM64);
    cudaFuncSetAttribute(k_rec, cudaFuncAttributeMaxDynamicSharedMemorySize, SMEM64);

    // launch 0: merged conversion + permutation
    k_prep<<<2048, 256>>>((const float4*)context, (const float4*)W_merge,
                          W_ih, W_hh, (const float4*)W_out, b_ih, b_hh);

    // launch 1: GEMM1  ctx = context @ Wm^T + b_merge (3-pass split-fp16)
    {
        dim3 g(HD / 64, NB / 64);  // (8,4)
        k_g64<3><<<g, 128, SMEM64>>>(ctx32, HD,
            ctxin_hi, ctxin_lo, ctxin_hi,
            wm_hi, wm_hi, wm_lo,
            b_merge, CAT);
    }
    // launch 2: split ctx
    k_split<<<(NB * HD + 255) / 256, 256>>>(ctx32, ctx_hi, ctx_lo, NB * HD);
    // launch 3: GEMM2  x_proj(perm) = ctx @ Wih_p^T + b_ih_p (3-pass)
    {
        dim3 g(G4 / 64, NB / 64);  // (32,4)
        k_g64<3><<<g, 128, SMEM64>>>(xproj, G4,
            ctx_hi, ctx_lo, ctx_hi,
            wih_hi, wih_hi, wih_lo,
            bihp, HD);
    }
    // launch 4: persistent LSTM recurrence (all TT steps)
    {
        dim3 g(G4 / 64, NB / 64);  // (32,4) = 128 CTAs
        k_rec<<<g, 128, SMEM64>>>(whhp, xproj, bhhp, cbuf, hall);
    }
    // launch 5: big GEMM  out[2048,32000] = H_all @ Wo^T + b_out
    {
        dim3 g(VOC / 128, (NB * TT) / 128);  // (250,16)
        k_gemm<1><<<g, 256, SMEM128>>>(out, VOC,
            hall, hall, hall,
            wo16, wo16, wo16,
            b_out, HD);
    }
}

// round 6
// speedup vs baseline: 1.2478x; 1.0357x over previous
#include <cuda_runtime.h>
#include <cuda_fp16.h>
#include <cstdint>
#include <cstddef>

#define DI __device__ __forceinline__

static constexpr int NB  = 256;     // batch
static constexpr int CAT = 1024;
static constexpr int HD  = 512;
static constexpr int VOC = 32000;
static constexpr int TT  = 8;
static constexpr int G4  = 4 * HD;  // 2048
static constexpr int REC_CTAS = (G4 / 64) * (NB / 64);  // 128

// ---------------- device scratch (static: no allocation) ----------------
__device__ __half d_ctxin_hi[NB * CAT];
__device__ __half d_ctxin_lo[NB * CAT];
__device__ __half d_wm_hi[HD * CAT];
__device__ __half d_wm_lo[HD * CAT];
__device__ __half d_wih_hi[G4 * HD];   // gate-interleaved rows
__device__ __half d_wih_lo[G4 * HD];   // gate-interleaved rows
__device__ __half d_whhp[G4 * HD];     // gate-interleaved rows
__device__ __half d_wo16[VOC * HD];
__device__ float  d_bihp[G4];          // permuted b_ih
__device__ float  d_bhhp[G4];          // permuted b_hh
__device__ __half d_ctx_hi[NB * HD];
__device__ __half d_ctx_lo[NB * HD];
__device__ float  d_xproj[NB * G4];    // gate-interleaved cols
__device__ float  d_cst[NB * HD];
__device__ __half d_h_hi[2][NB * HD];  // double-buffered across steps
__device__ __half d_h_lo[2][NB * HD];
__device__ __half d_hall[NB * TT * HD];
__device__ unsigned d_bar_cnt = 0;
__device__ unsigned d_bar_gen = 0;

// ---------------- PTX helpers ----------------
DI uint32_t smem_u32(const void* p) {
    uint32_t a;
    asm("{ .reg .u64 t; cvta.to.shared.u64 t, %1; cvt.u32.u64 %0, t; }"
        : "=r"(a) : "l"(p));
    return a;
}
DI void cp_async16(uint32_t dst, const void* src) {
    asm volatile("cp.async.cg.shared.global [%0], [%1], 16;"
                 :: "r"(dst), "l"(src) : "memory");
}
DI void cp_commit() { asm volatile("cp.async.commit_group;" ::: "memory"); }
template <int N>
DI void cp_wait() { asm volatile("cp.async.wait_group %0;" :: "n"(N) : "memory"); }

DI void ldsm_x4(uint32_t (&d)[4], uint32_t addr) {
    asm volatile("ldmatrix.sync.aligned.m8n8.x4.shared.b16 {%0,%1,%2,%3}, [%4];"
                 : "=r"(d[0]), "=r"(d[1]), "=r"(d[2]), "=r"(d[3]) : "r"(addr));
}
DI void mma16816(float (&c)[4], const uint32_t (&a)[4], uint32_t b0, uint32_t b1) {
    asm volatile(
        "mma.sync.aligned.m16n8k16.row.col.f32.f16.f16.f32 "
        "{%0,%1,%2,%3}, {%4,%5,%6,%7}, {%8,%9}, {%0,%1,%2,%3};"
        : "+f"(c[0]), "+f"(c[1]), "+f"(c[2]), "+f"(c[3])
        : "r"(a[0]), "r"(a[1]), "r"(a[2]), "r"(a[3]), "r"(b0), "r"(b1));
}

DI void split1(float v, __half& hi, __half& lo) {
    __half h = __float2half_rn(v);
    hi = h;
    lo = __float2half_rn(v - __half2float(h));
}
DI void split4(float4 v, __half2* hi2, __half2* lo2) {
    __half2 h01 = __floats2half2_rn(v.x, v.y);
    __half2 h23 = __floats2half2_rn(v.z, v.w);
    float2 f01 = __half22float2(h01);
    float2 f23 = __half22float2(h23);
    hi2[0] = h01; hi2[1] = h23;
    lo2[0] = __floats2half2_rn(v.x - f01.x, v.y - f01.y);
    lo2[1] = __floats2half2_rn(v.z - f23.x, v.w - f23.y);
}

// device-wide sense barrier (all REC_CTAS CTAs co-resident)
DI void grid_barrier() {
    __syncthreads();
    if (threadIdx.x == 0) {
        __threadfence();
        unsigned g;
        asm volatile("ld.acquire.gpu.global.u32 %0, [%1];"
                     : "=r"(g) : "l"(&d_bar_gen));
        unsigned v = atomicAdd(&d_bar_cnt, 1u);
        if (v == REC_CTAS - 1) {
            d_bar_cnt = 0;
            asm volatile("red.release.gpu.global.add.u32 [%0], 1;"
                         :: "l"(&d_bar_gen) : "memory");
        } else {
            unsigned cur;
            do {
                asm volatile("ld.acquire.gpu.global.u32 %0, [%1];"
                             : "=r"(cur) : "l"(&d_bar_gen));
            } while (cur == g);
        }
    }
    __syncthreads();
}

// ---------------- merged conversion / permutation kernel ----------------
__global__ void k_prep(const float4* __restrict__ ctx, const float4* __restrict__ wm,
                       const float* __restrict__ wih, const float* __restrict__ whh,
                       const float4* __restrict__ wo,
                       const float* __restrict__ bih, const float* __restrict__ bhh) {
    constexpr int R0 = NB * CAT / 4;
    constexpr int R1 = R0 + HD * CAT / 4;
    constexpr int R2 = R1 + G4 * HD / 4;
    constexpr int R3 = R2 + G4 * HD / 4;
    constexpr int R4 = R3 + VOC * HD / 4;
    constexpr int HD4 = HD / 4;

    if (blockIdx.x == 0) {
        for (int p = threadIdx.x; p < G4; p += blockDim.x) {
            int j = p >> 2, q = p & 3;
            d_bihp[p] = bih[q * HD + j];
            d_bhhp[p] = bhh[q * HD + j];
        }
    }
    int stride = gridDim.x * blockDim.x;
    for (int u = blockIdx.x * blockDim.x + threadIdx.x; u < R4; u += stride) {
        if (u < R0) {
            split4(ctx[u], (__half2*)d_ctxin_hi + 2 * u, (__half2*)d_ctxin_lo + 2 * u);
        } else if (u < R1) {
            int v = u - R0;
            split4(wm[v], (__half2*)d_wm_hi + 2 * v, (__half2*)d_wm_lo + 2 * v);
        } else if (u < R2) {
            int v = u - R1;
            int p = v >> 7, c4 = v & (HD4 - 1);
            int j = p >> 2, q = p & 3;
            float4 w = *reinterpret_cast<const float4*>(wih + (size_t)(q * HD + j) * HD + c4 * 4);
            split4(w, (__half2*)d_wih_hi + 2 * v, (__half2*)d_wih_lo + 2 * v);
        } else if (u < R3) {
            int v = u - R2;
            int p = v >> 7, c4 = v & (HD4 - 1);
            int j = p >> 2, q = p & 3;
            float4 w = *reinterpret_cast<const float4*>(whh + (size_t)(q * HD + j) * HD + c4 * 4);
            __half2* o = (__half2*)d_whhp + 2 * v;
            o[0] = __floats2half2_rn(w.x, w.y);
            o[1] = __floats2half2_rn(w.z, w.w);
        } else {
            int v = u - R3;
            float4 w = wo[v];
            __half2* o = (__half2*)d_wo16 + 2 * v;
            o[0] = __floats2half2_rn(w.x, w.y);
            o[1] = __floats2half2_rn(w.z, w.w);
        }
    }
}

// ---------------- 64x64 HMMA GEMM, 128 thr, 3-stage -------------------------
// MODE 0: C = acc + bias (fp32). MODE 2: split-fp16 store to Chi/Clo.
template <int NPASS, int MODE>
__global__ void __launch_bounds__(128)
k_g64(float* __restrict__ C, __half* __restrict__ Chi, __half* __restrict__ Clo,
      int ldc,
      const __half* __restrict__ A0, const __half* __restrict__ A1,
      const __half* __restrict__ A2,
      const __half* __restrict__ B0, const __half* __restrict__ B1,
      const __half* __restrict__ B2,
      const float* __restrict__ bias, int K) {
    extern __shared__ char smem[];
    constexpr int TILE_B = 64 * 128;
    constexpr int STG    = 2 * TILE_B;

    const uint32_t sb = smem_u32(smem);
    const int tid    = threadIdx.x;
    const int lane   = tid & 31;
    const int wid    = tid >> 5;
    const int warp_m = wid & 1;
    const int warp_n = wid >> 1;

    const int mBase = blockIdx.y * 64;
    const int nBase = blockIdx.x * 64;

    const __half* Ap[3] = {A0, A1, A2};
    const __half* Bp[3] = {B0, B1, B2};
    const int kch   = K >> 6;
    const int total = NPASS * kch;

    const int ldr = tid >> 3;
    const int ldg = tid & 7;

    auto load_chunk = [&](int ch) {
        const int st   = ch % 3;
        const int pass = ch / kch;
        const int kc   = ch - pass * kch;
        const __half* Ag = Ap[pass] + (size_t)mBase * K + kc * 64;
        const __half* Bg = Bp[pass] + (size_t)nBase * K + kc * 64;
        const uint32_t a_u = sb + st * STG;
        const uint32_t b_u = a_u + TILE_B;
#pragma unroll
        for (int it = 0; it < 4; ++it) {
            int r = ldr + it * 16;
            uint32_t off = (uint32_t)(r * 128 + (ldg * 16 ^ ((r & 7) << 4)));
            cp_async16(a_u + off, Ag + (size_t)r * K + ldg * 8);
            cp_async16(b_u + off, Bg + (size_t)r * K + ldg * 8);
        }
        cp_commit();
    };

    float acc[2][4][4];
#pragma unroll
    for (int mi = 0; mi < 2; ++mi)
#pragma unroll
        for (int ni = 0; ni < 4; ++ni)
#pragma unroll
            for (int q = 0; q < 4; ++q) acc[mi][ni][q] = 0.f;

    int arow[2], brow[2];
#pragma unroll
    for (int mi = 0; mi < 2; ++mi)
        arow[mi] = warp_m * 32 + mi * 16 + (lane & 7) + ((lane >> 3) & 1) * 8;
#pragma unroll
    for (int nq = 0; nq < 2; ++nq)
        brow[nq] = warp_n * 32 + nq * 16 + (lane & 7) + (lane >> 4) * 8;
    const int akb = (lane >> 4) * 16;
    const int bkb = ((lane >> 3) & 1) * 16;

    load_chunk(0);
    load_chunk(1);
    for (int ch = 0; ch < total; ++ch) {
        if (ch + 1 < total) cp_wait<1>(); else cp_wait<0>();
        __syncthreads();
        if (ch + 2 < total) load_chunk(ch + 2);

        const uint32_t a_u = sb + (ch % 3) * STG;
        const uint32_t b_u = a_u + TILE_B;
#pragma unroll
        for (int ks = 0; ks < 4; ++ks) {
            uint32_t aF[2][4];
#pragma unroll
            for (int mi = 0; mi < 2; ++mi) {
                int r = arow[mi], kb = ks * 32 + akb;
                ldsm_x4(aF[mi], a_u + r * 128 + (kb ^ ((r & 7) << 4)));
            }
            uint32_t bF[2][4];
#pragma unroll
            for (int nq = 0; nq < 2; ++nq) {
                int r = brow[nq], kb = ks * 32 + bkb;
                ldsm_x4(bF[nq], b_u + r * 128 + (kb ^ ((r & 7) << 4)));
            }
#pragma unroll
            for (int mi = 0; mi < 2; ++mi)
#pragma unroll
                for (int ni = 0; ni < 4; ++ni)
                    mma16816(acc[mi][ni], aF[mi],
                             bF[ni >> 1][(ni & 1) * 2], bF[ni >> 1][(ni & 1) * 2 + 1]);
        }
    }

    const int m0 = mBase + warp_m * 32;
    const int n0 = nBase + warp_n * 32;
#pragma unroll
    for (int ni = 0; ni < 4; ++ni) {
        int col = n0 + ni * 8 + 2 * (lane & 3);
        float2 bv = *reinterpret_cast<const float2*>(bias + col);
#pragma unroll
        for (int mi = 0; mi < 2; ++mi) {
            int row = m0 + mi * 16 + (lane >> 2);
            float2 v0 = {acc[mi][ni][0] + bv.x, acc[mi][ni][1] + bv.y};
            float2 v1 = {acc[mi][ni][2] + bv.x, acc[mi][ni][3] + bv.y};
            if (MODE == 0) {
                *reinterpret_cast<float2*>(C + (size_t)row * ldc + col) = v0;
                *reinterpret_cast<float2*>(C + (size_t)(row + 8) * ldc + col) = v1;
            } else {
                __half hx, lx, hy, ly;
                split1(v0.x, hx, lx); split1(v0.y, hy, ly);
                *reinterpret_cast<__half2*>(Chi + (size_t)row * ldc + col) =
                    __halves2half2(hx, hy);
                *reinterpret_cast<__half2*>(Clo + (size_t)row * ldc + col) =
                    __halves2half2(lx, ly);
                split1(v1.x, hx, lx); split1(v1.y, hy, ly);
                *reinterpret_cast<__half2*>(Chi + (size_t)(row + 8) * ldc + col) =
                    __halves2half2(hx, hy);
                *reinterpret_cast<__half2*>(Clo + (size_t)(row + 8) * ldc + col) =
                    __halves2half2(lx, ly);
            }
        }
    }
}

// ---------------- BIG logits GEMM: 128x128 CTA tile, 128 thr (4 warps of
// 64x64), 3-stage cp.async pipeline. Intensity 16 MAC/B -> tensor-bound. -----
__global__ void __launch_bounds__(128)
k_big(float* __restrict__ C, int ldc,
      const __half* __restrict__ A, const __half* __restrict__ B,
      const float* __restrict__ bias, int K) {
    extern __shared__ char smem[];
    constexpr int TILE_B = 128 * 128;   // 16 KB per operand per stage
    constexpr int STG    = 2 * TILE_B;  // 32 KB per stage

    const uint32_t sb = smem_u32(smem);
    const int tid    = threadIdx.x;
    const int lane   = tid & 31;
    const int wid    = tid >> 5;
    const int warp_m = wid & 1;   // 2 M-slices of 64
    const int warp_n = wid >> 1;  // 2 N-slices of 64

    const int mBase = blockIdx.y * 128;
    const int nBase = blockIdx.x * 128;
    const int total = K >> 6;     // 8 chunks

    const int ldr = tid >> 3;     // 0..15
    const int ldg = tid & 7;

    auto load_chunk = [&](int ch) {
        const int st = ch % 3;
        const __half* Ag = A + (size_t)mBase * K + ch * 64;
        const __half* Bg = B + (size_t)nBase * K + ch * 64;
        const uint32_t a_u = sb + st * STG;
        const uint32_t b_u = a_u + TILE_B;
#pragma unroll
        for (int it = 0; it < 8; ++it) {
            int r = ldr + it * 16;
            uint32_t off = (uint32_t)(r * 128 + (ldg * 16 ^ ((r & 7) << 4)));
            cp_async16(a_u + off, Ag + (size_t)r * K + ldg * 8);
            cp_async16(b_u + off, Bg + (size_t)r * K + ldg * 8);
        }
        cp_commit();
    };

    float acc[4][8][4];   // 4 mi x 8 ni x 4 = 128 fp32
#pragma unroll
    for (int mi = 0; mi < 4; ++mi)
#pragma unroll
        for (int ni = 0; ni < 8; ++ni)
#pragma unroll
            for (int q = 0; q < 4; ++q) acc[mi][ni][q] = 0.f;

    int arow[4], brow[4];
#pragma unroll
    for (int mi = 0; mi < 4; ++mi)
        arow[mi] = warp_m * 64 + mi * 16 + (lane & 7) + ((lane >> 3) & 1) * 8;
#pragma unroll
    for (int nq = 0; nq < 4; ++nq)
        brow[nq] = warp_n * 64 + nq * 16 + (lane & 7) + (lane >> 4) * 8;
    const int akb = (lane >> 4) * 16;
    const int bkb = ((lane >> 3) & 1) * 16;

    load_chunk(0);
    load_chunk(1);

    for (int ch = 0; ch < total; ++ch) {
        if (ch + 1 < total) cp_wait<1>(); else cp_wait<0>();
        __syncthreads();
        if (ch + 2 < total) load_chunk(ch + 2);

        const uint32_t a_u = sb + (ch % 3) * STG;
        const uint32_t b_u = a_u + TILE_B;
#pragma unroll
        for (int ks = 0; ks < 4; ++ks) {
            uint32_t aF[4][4];
#pragma unroll
            for (int mi = 0; mi < 4; ++mi) {
                int r = arow[mi], kb = ks * 32 + akb;
                ldsm_x4(aF[mi], a_u + r * 128 + (kb ^ ((r & 7) << 4)));
            }
            uint32_t bF[4][4];
#pragma unroll
            for (int nq = 0; nq < 4; ++nq) {
                int r = brow[nq], kb = ks * 32 + bkb;
                ldsm_x4(bF[nq], b_u + r * 128 + (kb ^ ((r & 7) << 4)));
            }
#pragma unroll
            for (int mi = 0; mi < 4; ++mi)
#pragma unroll
                for (int ni = 0; ni < 8; ++ni)
                    mma16816(acc[mi][ni], aF[mi],
                             bF[ni >> 1][(ni & 1) * 2], bF[ni >> 1][(ni & 1) * 2 + 1]);
        }
    }

    const int m0 = mBase + warp_m * 64;
    const int n0 = nBase + warp_n * 64;
#pragma unroll
    for (int ni = 0; ni < 8; ++ni) {
        int col = n0 + ni * 8 + 2 * (lane & 3);
        float2 bv = *reinterpret_cast<const float2*>(bias + col);
#pragma unroll
        for (int mi = 0; mi < 4; ++mi) {
            int row = m0 + mi * 16 + (lane >> 2);
            float2 v0 = {acc[mi][ni][0] + bv.x, acc[mi][ni][1] + bv.y};
            float2 v1 = {acc[mi][ni][2] + bv.x, acc[mi][ni][3] + bv.y};
            *reinterpret_cast<float2*>(C + (size_t)row * ldc + col) = v0;
            *reinterpret_cast<float2*>(C + (size_t)(row + 8) * ldc + col) = v1;
        }
    }
}

// ---------------- persistent LSTM recurrence: all TT steps in one kernel ----
__global__ void __launch_bounds__(128)
k_rec(const __half* __restrict__ Bw, const float* __restrict__ xproj,
      const float* __restrict__ bhhp, float* __restrict__ cst,
      __half* __restrict__ hall) {
    extern __shared__ char smem[];
    constexpr int TILE_B = 64 * 128;
    constexpr int STG    = 2 * TILE_B;

    const uint32_t sb = smem_u32(smem);
    const int tid    = threadIdx.x;
    const int lane   = tid & 31;
    const int wid    = tid >> 5;
    const int warp_m = wid & 1;
    const int warp_n = wid >> 1;

    const int mBase = blockIdx.y * 64;
    const int nBase = blockIdx.x * 64;

    const int ldr = tid >> 3;
    const int ldg = tid & 7;

    int arow[2], brow[2];
#pragma unroll
    for (int mi = 0; mi < 2; ++mi)
        arow[mi] = warp_m * 32 + mi * 16 + (lane & 7) + ((lane >> 3) & 1) * 8;
#pragma unroll
    for (int nq = 0; nq < 2; ++nq)
        brow[nq] = warp_n * 32 + nq * 16 + (lane & 7) + (lane >> 4) * 8;
    const int akb = (lane >> 4) * 16;
    const int bkb = ((lane >> 3) & 1) * 16;

    for (int t = 0; t < TT; ++t) {
        float acc[2][4][4];
#pragma unroll
        for (int mi = 0; mi < 2; ++mi)
#pragma unroll
            for (int ni = 0; ni < 4; ++ni)
#pragma unroll
                for (int q = 0; q < 4; ++q) acc[mi][ni][q] = 0.f;

        if (t > 0) {
            const int rd = t & 1;
            const __half* Ap[2] = {d_h_hi[rd], d_h_lo[rd]};
            const int total = 16;  // 2 passes x 8 chunks

            auto load_chunk = [&](int ch) {
                const int st   = ch % 3;
                const int pass = ch >> 3;
                const int kc   = ch & 7;
                const __half* Ag = Ap[pass] + (size_t)mBase * HD + kc * 64;
                const __half* Bg = Bw + (size_t)nBase * HD + kc * 64;
                const uint32_t a_u = sb + st * STG;
                const uint32_t b_u = a_u + TILE_B;
#pragma unroll
                for (int it = 0; it < 4; ++it) {
                    int r = ldr + it * 16;
                    uint32_t off = (uint32_t)(r * 128 + (ldg * 16 ^ ((r & 7) << 4)));
                    cp_async16(a_u + off, Ag + (size_t)r * HD + ldg * 8);
                    cp_async16(b_u + off, Bg + (size_t)r * HD + ldg * 8);
                }
                cp_commit();
            };

            load_chunk(0);
            load_chunk(1);
            for (int ch = 0; ch < total; ++ch) {
                if (ch + 1 < total) cp_wait<1>(); else cp_wait<0>();
                __syncthreads();
                if (ch + 2 < total) load_chunk(ch + 2);

                const uint32_t a_u = sb + (ch % 3) * STG;
                const uint32_t b_u = a_u + TILE_B;
#pragma unroll
                for (int ks = 0; ks < 4; ++ks) {
                    uint32_t aF[2][4];
#pragma unroll
                    for (int mi = 0; mi < 2; ++mi) {
                        int r = arow[mi], kb = ks * 32 + akb;
                        ldsm_x4(aF[mi], a_u + r * 128 + (kb ^ ((r & 7) << 4)));
                    }
                    uint32_t bF[2][4];
#pragma unroll
                    for (int nq = 0; nq < 2; ++nq) {
                        int r = brow[nq], kb = ks * 32 + bkb;
                        ldsm_x4(bF[nq], b_u + r * 128 + (kb ^ ((r & 7) << 4)));
                    }
#pragma unroll
                    for (int mi = 0; mi < 2; ++mi)
#pragma unroll
                        for (int ni = 0; ni < 4; ++ni)
                            mma16816(acc[mi][ni], aF[mi],
                                     bF[ni >> 1][(ni & 1) * 2], bF[ni >> 1][(ni & 1) * 2 + 1]);
                }
            }
        }

        // ---- cell epilogue: write h into buffer (t+1)&1 ----
        {
            const int wr = (t + 1) & 1;
            __half* hhi = d_h_hi[wr];
            __half* hlo = d_h_lo[wr];
            const int m0  = mBase + warp_m * 32;
            const int n0g = nBase + warp_n * 32;
            const int a   = lane & 3;
            const int rb  = lane >> 2;
#pragma unroll
            for (int ni = 0; ni < 4; ++ni) {
                int col = n0g + ni * 8 + 2 * a;
                float2 bb = *reinterpret_cast<const float2*>(bhhp + col);
#pragma unroll
                for (int mi = 0; mi < 2; ++mi) {
#pragma unroll
                    for (int hq = 0; hq < 2; ++hq) {
                        int row = m0 + mi * 16 + rb + hq * 8;
                        float2 xp = *reinterpret_cast<const float2*>(
                            xproj + (size_t)row * G4 + col);
                        float g0 = acc[mi][ni][hq * 2 + 0] + xp.x + bb.x;
                        float g1 = acc[mi][ni][hq * 2 + 1] + xp.y + bb.y;
                        float o0 = __shfl_xor_sync(0xFFFFFFFFu, g0, 1);
                        float o1 = __shfl_xor_sync(0xFFFFFFFFu, g1, 1);
                        if ((a & 1) == 0) {
                            float si = 1.f / (1.f + expf(-g0));
                            float sf = 1.f / (1.f + expf(-g1));
                            float tg = tanhf(o0);
                            float so = 1.f / (1.f + expf(-o1));
                            int j = (n0g >> 2) + 2 * ni + (a >> 1);
                            float cp = (t == 0) ? 0.f : cst[(size_t)row * HD + j];
                            float cn = sf * cp + si * tg;
                            cst[(size_t)row * HD + j] = cn;
                            float h = so * tanhf(cn);
                            __half hh = __float2half_rn(h);
                            hhi[(size_t)row * HD + j] = hh;
                            hlo[(size_t)row * HD + j] = __float2half_rn(h - __half2float(hh));
                            hall[((size_t)row * TT + t) * HD + j] = hh;
                        }
                    }
                }
            }
        }

        if (t + 1 < TT) grid_barrier();
    }
}

// ---------------- host orchestration ----------------
extern "C" void kernel_launch(void* const* d_in, const int* in_sizes, int n_in,
                              void* d_out, int out_size) {
    const float* context = (const float*)d_in[0];
    const float* W_merge = (const float*)d_in[1];
    const float* b_merge = (const float*)d_in[2];
    const float* W_ih    = (const float*)d_in[3];
    const float* W_hh    = (const float*)d_in[4];
    const float* b_ih    = (const float*)d_in[5];
    const float* b_hh    = (const float*)d_in[6];
    const float* W_out   = (const float*)d_in[7];
    const float* b_out   = (const float*)d_in[8];
    float* out = (float*)d_out;

    __half *ctxin_hi, *ctxin_lo, *wm_hi, *wm_lo, *wih_hi, *wih_lo, *whhp, *wo16;
    __half *ctx_hi, *ctx_lo, *hall;
    float *xproj, *cbuf, *bihp, *bhhp;
    cudaGetSymbolAddress((void**)&ctxin_hi, d_ctxin_hi);
    cudaGetSymbolAddress((void**)&ctxin_lo, d_ctxin_lo);
    cudaGetSymbolAddress((void**)&wm_hi, d_wm_hi);
    cudaGetSymbolAddress((void**)&wm_lo, d_wm_lo);
    cudaGetSymbolAddress((void**)&wih_hi, d_wih_hi);
    cudaGetSymbolAddress((void**)&wih_lo, d_wih_lo);
    cudaGetSymbolAddress((void**)&whhp, d_whhp);
    cudaGetSymbolAddress((void**)&wo16, d_wo16);
    cudaGetSymbolAddress((void**)&bihp, d_bihp);
    cudaGetSymbolAddress((void**)&bhhp, d_bhhp);
    cudaGetSymbolAddress((void**)&ctx_hi, d_ctx_hi);
    cudaGetSymbolAddress((void**)&ctx_lo, d_ctx_lo);
    cudaGetSymbolAddress((void**)&xproj, d_xproj);
    cudaGetSymbolAddress((void**)&cbuf, d_cst);
    cudaGetSymbolAddress((void**)&hall, d_hall);

    const int SMEM64  = 3 * 2 * 64 * 128;    // 49152
    const int SMEMBIG = 3 * 2 * 128 * 128;   // 98304
    cudaFuncSetAttribute(k_g64<3, 0>, cudaFuncAttributeMaxDynamicSharedMemorySize, SMEM64);
    cudaFuncSetAttribute(k_g64<3, 2>, cudaFuncAttributeMaxDynamicSharedMemorySize, SMEM64);
    cudaFuncSetAttribute(k_rec, cudaFuncAttributeMaxDynamicSharedMemorySize, SMEM64);
    cudaFuncSetAttribute(k_big, cudaFuncAttributeMaxDynamicSharedMemorySize, SMEMBIG);

    // launch 0: merged conversion + permutation
    k_prep<<<2048, 256>>>((const float4*)context, (const float4*)W_merge,
                          W_ih, W_hh, (const float4*)W_out, b_ih, b_hh);

    // launch 1: GEMM1  ctx = context @ Wm^T + b_merge (3-pass), split-store
    {
        dim3 g(HD / 64, NB / 64);  // (8,4)
        k_g64<3, 2><<<g, 128, SMEM64>>>(nullptr, ctx_hi, ctx_lo, HD,
            ctxin_hi, ctxin_lo, ctxin_hi,
            wm_hi, wm_hi, wm_lo,
            b_merge, CAT);
    }
    // launch 2: GEMM2  x_proj(perm) = ctx @ Wih_p^T + b_ih_p (3-pass)
    {
        dim3 g(G4 / 64, NB / 64);  // (32,4)
        k_g64<3, 0><<<g, 128, SMEM64>>>(xproj, nullptr, nullptr, G4,
            ctx_hi, ctx_lo, ctx_hi,
            wih_hi, wih_hi, wih_lo,
            bihp, HD);
    }
    // launch 3: persistent LSTM recurrence (all TT steps)
    {
        dim3 g(G4 / 64, NB / 64);  // (32,4) = 128 CTAs
        k_rec<<<g, 128, SMEM64>>>(whhp, xproj, bhhp, cbuf, hall);
    }
    // launch 4: big GEMM  out[2048,32000] = H_all @ Wo^T + b_out
    {
        dim3 g(VOC / 128, (NB * TT) / 128);  // (250,16)
        k_big<<<g, 128, SMEMBIG>>>(out, VOC, hall, wo16, b_out, HD);
    }
}

// round 7
// speedup vs baseline: 1.2957x; 1.0384x over previous
#include <cuda_runtime.h>
#include <cuda_fp16.h>
#include <cstdint>
#include <cstddef>

#define DI __device__ __forceinline__

static constexpr int NB  = 256;     // batch
static constexpr int CAT = 1024;
static constexpr int HD  = 512;
static constexpr int VOC = 32000;
static constexpr int TT  = 8;
static constexpr int G4  = 4 * HD;  // 2048
static constexpr int REC_CTAS = (G4 / 64) * (NB / 64);  // 128

// ---------------- device scratch (static: no allocation) ----------------
__device__ __half d_ctxin_hi[NB * CAT];
__device__ __half d_ctxin_lo[NB * CAT];
__device__ __half d_wm_hi[HD * CAT];
__device__ __half d_wm_lo[HD * CAT];
__device__ __half d_wih_hi[G4 * HD];   // gate-interleaved rows
__device__ __half d_wih_lo[G4 * HD];   // gate-interleaved rows
__device__ __half d_whhp[G4 * HD];     // gate-interleaved rows
__device__ __half d_wo16[VOC * HD];
__device__ float  d_bihp[G4];          // permuted b_ih
__device__ float  d_bhhp[G4];          // permuted b_hh
__device__ __half d_ctx_hi[NB * HD];
__device__ __half d_ctx_lo[NB * HD];
__device__ float  d_xproj[NB * G4];    // gate-interleaved cols
__device__ float  d_cst[NB * HD];
__device__ __half d_h_hi[2][NB * HD];  // double-buffered across steps
__device__ __half d_h_lo[2][NB * HD];
__device__ __half d_hall[NB * TT * HD];
__device__ unsigned d_bar_cnt = 0;
__device__ unsigned d_bar_gen = 0;

// ---------------- PTX helpers ----------------
DI uint32_t smem_u32(const void* p) {
    uint32_t a;
    asm("{ .reg .u64 t; cvta.to.shared.u64 t, %1; cvt.u32.u64 %0, t; }"
        : "=r"(a) : "l"(p));
    return a;
}
DI void cp_async16(uint32_t dst, const void* src) {
    asm volatile("cp.async.cg.shared.global [%0], [%1], 16;"
                 :: "r"(dst), "l"(src) : "memory");
}
DI void cp_commit() { asm volatile("cp.async.commit_group;" ::: "memory"); }
template <int N>
DI void cp_wait() { asm volatile("cp.async.wait_group %0;" :: "n"(N) : "memory"); }

DI void ldsm_x4(uint32_t (&d)[4], uint32_t addr) {
    asm volatile("ldmatrix.sync.aligned.m8n8.x4.shared.b16 {%0,%1,%2,%3}, [%4];"
                 : "=r"(d[0]), "=r"(d[1]), "=r"(d[2]), "=r"(d[3]) : "r"(addr));
}
DI void mma16816(float (&c)[4], const uint32_t (&a)[4], uint32_t b0, uint32_t b1) {
    asm volatile(
        "mma.sync.aligned.m16n8k16.row.col.f32.f16.f16.f32 "
        "{%0,%1,%2,%3}, {%4,%5,%6,%7}, {%8,%9}, {%0,%1,%2,%3};"
        : "+f"(c[0]), "+f"(c[1]), "+f"(c[2]), "+f"(c[3])
        : "r"(a[0]), "r"(a[1]), "r"(a[2]), "r"(a[3]), "r"(b0), "r"(b1));
}

DI void split1(float v, __half& hi, __half& lo) {
    __half h = __float2half_rn(v);
    hi = h;
    lo = __float2half_rn(v - __half2float(h));
}
DI void split4(float4 v, __half2* hi2, __half2* lo2) {
    __half2 h01 = __floats2half2_rn(v.x, v.y);
    __half2 h23 = __floats2half2_rn(v.z, v.w);
    float2 f01 = __half22float2(h01);
    float2 f23 = __half22float2(h23);
    hi2[0] = h01; hi2[1] = h23;
    lo2[0] = __floats2half2_rn(v.x - f01.x, v.y - f01.y);
    lo2[1] = __floats2half2_rn(v.z - f23.x, v.w - f23.y);
}

// device-wide sense barrier (all REC_CTAS CTAs co-resident)
DI void grid_barrier() {
    __syncthreads();
    if (threadIdx.x == 0) {
        __threadfence();
        unsigned g;
        asm volatile("ld.acquire.gpu.global.u32 %0, [%1];"
                     : "=r"(g) : "l"(&d_bar_gen));
        unsigned v = atomicAdd(&d_bar_cnt, 1u);
        if (v == REC_CTAS - 1) {
            d_bar_cnt = 0;
            asm volatile("red.release.gpu.global.add.u32 [%0], 1;"
                         :: "l"(&d_bar_gen) : "memory");
        } else {
            unsigned cur;
            do {
                asm volatile("ld.acquire.gpu.global.u32 %0, [%1];"
                             : "=r"(cur) : "l"(&d_bar_gen));
            } while (cur == g);
        }
    }
    __syncthreads();
}

// ---------------- merged conversion / permutation kernel ----------------
__global__ void k_prep(const float4* __restrict__ ctx, const float4* __restrict__ wm,
                       const float* __restrict__ wih, const float* __restrict__ whh,
                       const float4* __restrict__ wo,
                       const float* __restrict__ bih, const float* __restrict__ bhh) {
    constexpr int R0 = NB * CAT / 4;
    constexpr int R1 = R0 + HD * CAT / 4;
    constexpr int R2 = R1 + G4 * HD / 4;
    constexpr int R3 = R2 + G4 * HD / 4;
    constexpr int R4 = R3 + VOC * HD / 4;
    constexpr int HD4 = HD / 4;

    if (blockIdx.x == 0) {
        for (int p = threadIdx.x; p < G4; p += blockDim.x) {
            int j = p >> 2, q = p & 3;
            d_bihp[p] = bih[q * HD + j];
            d_bhhp[p] = bhh[q * HD + j];
        }
    }
    int stride = gridDim.x * blockDim.x;
    for (int u = blockIdx.x * blockDim.x + threadIdx.x; u < R4; u += stride) {
        if (u < R0) {
            split4(ctx[u], (__half2*)d_ctxin_hi + 2 * u, (__half2*)d_ctxin_lo + 2 * u);
        } else if (u < R1) {
            int v = u - R0;
            split4(wm[v], (__half2*)d_wm_hi + 2 * v, (__half2*)d_wm_lo + 2 * v);
        } else if (u < R2) {
            int v = u - R1;
            int p = v >> 7, c4 = v & (HD4 - 1);
            int j = p >> 2, q = p & 3;
            float4 w = *reinterpret_cast<const float4*>(wih + (size_t)(q * HD + j) * HD + c4 * 4);
            split4(w, (__half2*)d_wih_hi + 2 * v, (__half2*)d_wih_lo + 2 * v);
        } else if (u < R3) {
            int v = u - R2;
            int p = v >> 7, c4 = v & (HD4 - 1);
            int j = p >> 2, q = p & 3;
            float4 w = *reinterpret_cast<const float4*>(whh + (size_t)(q * HD + j) * HD + c4 * 4);
            __half2* o = (__half2*)d_whhp + 2 * v;
            o[0] = __floats2half2_rn(w.x, w.y);
            o[1] = __floats2half2_rn(w.z, w.w);
        } else {
            int v = u - R3;
            float4 w = wo[v];
            __half2* o = (__half2*)d_wo16 + 2 * v;
            o[0] = __floats2half2_rn(w.x, w.y);
            o[1] = __floats2half2_rn(w.z, w.w);
        }
    }
}

// ---------------- 64x64 HMMA GEMM, 128 thr, 3-stage -------------------------
// MODE 0: C = acc + bias (fp32). MODE 2: split-fp16 store to Chi/Clo.
template <int NPASS, int MODE>
__global__ void __launch_bounds__(128)
k_g64(float* __restrict__ C, __half* __restrict__ Chi, __half* __restrict__ Clo,
      int ldc,
      const __half* __restrict__ A0, const __half* __restrict__ A1,
      const __half* __restrict__ A2,
      const __half* __restrict__ B0, const __half* __restrict__ B1,
      const __half* __restrict__ B2,
      const float* __restrict__ bias, int K) {
    extern __shared__ char smem[];
    constexpr int TILE_B = 64 * 128;
    constexpr int STG    = 2 * TILE_B;

    const uint32_t sb = smem_u32(smem);
    const int tid    = threadIdx.x;
    const int lane   = tid & 31;
    const int wid    = tid >> 5;
    const int warp_m = wid & 1;
    const int warp_n = wid >> 1;

    const int mBase = blockIdx.y * 64;
    const int nBase = blockIdx.x * 64;

    const __half* Ap[3] = {A0, A1, A2};
    const __half* Bp[3] = {B0, B1, B2};
    const int kch   = K >> 6;
    const int total = NPASS * kch;

    const int ldr = tid >> 3;
    const int ldg = tid & 7;

    auto load_chunk = [&](int ch) {
        const int st   = ch % 3;
        const int pass = ch / kch;
        const int kc   = ch - pass * kch;
        const __half* Ag = Ap[pass] + (size_t)mBase * K + kc * 64;
        const __half* Bg = Bp[pass] + (size_t)nBase * K + kc * 64;
        const uint32_t a_u = sb + st * STG;
        const uint32_t b_u = a_u + TILE_B;
#pragma unroll
        for (int it = 0; it < 4; ++it) {
            int r = ldr + it * 16;
            uint32_t off = (uint32_t)(r * 128 + (ldg * 16 ^ ((r & 7) << 4)));
            cp_async16(a_u + off, Ag + (size_t)r * K + ldg * 8);
            cp_async16(b_u + off, Bg + (size_t)r * K + ldg * 8);
        }
        cp_commit();
    };

    float acc[2][4][4];
#pragma unroll
    for (int mi = 0; mi < 2; ++mi)
#pragma unroll
        for (int ni = 0; ni < 4; ++ni)
#pragma unroll
            for (int q = 0; q < 4; ++q) acc[mi][ni][q] = 0.f;

    int arow[2], brow[2];
#pragma unroll
    for (int mi = 0; mi < 2; ++mi)
        arow[mi] = warp_m * 32 + mi * 16 + (lane & 7) + ((lane >> 3) & 1) * 8;
#pragma unroll
    for (int nq = 0; nq < 2; ++nq)
        brow[nq] = warp_n * 32 + nq * 16 + (lane & 7) + (lane >> 4) * 8;
    const int akb = (lane >> 4) * 16;
    const int bkb = ((lane >> 3) & 1) * 16;

    load_chunk(0);
    load_chunk(1);
    for (int ch = 0; ch < total; ++ch) {
        if (ch + 1 < total) cp_wait<1>(); else cp_wait<0>();
        __syncthreads();
        if (ch + 2 < total) load_chunk(ch + 2);

        const uint32_t a_u = sb + (ch % 3) * STG;
        const uint32_t b_u = a_u + TILE_B;
#pragma unroll
        for (int ks = 0; ks < 4; ++ks) {
            uint32_t aF[2][4];
#pragma unroll
            for (int mi = 0; mi < 2; ++mi) {
                int r = arow[mi], kb = ks * 32 + akb;
                ldsm_x4(aF[mi], a_u + r * 128 + (kb ^ ((r & 7) << 4)));
            }
            uint32_t bF[2][4];
#pragma unroll
            for (int nq = 0; nq < 2; ++nq) {
                int r = brow[nq], kb = ks * 32 + bkb;
                ldsm_x4(bF[nq], b_u + r * 128 + (kb ^ ((r & 7) << 4)));
            }
#pragma unroll
            for (int mi = 0; mi < 2; ++mi)
#pragma unroll
                for (int ni = 0; ni < 4; ++ni)
                    mma16816(acc[mi][ni], aF[mi],
                             bF[ni >> 1][(ni & 1) * 2], bF[ni >> 1][(ni & 1) * 2 + 1]);
        }
    }

    const int m0 = mBase + warp_m * 32;
    const int n0 = nBase + warp_n * 32;
#pragma unroll
    for (int ni = 0; ni < 4; ++ni) {
        int col = n0 + ni * 8 + 2 * (lane & 3);
        float2 bv = *reinterpret_cast<const float2*>(bias + col);
#pragma unroll
        for (int mi = 0; mi < 2; ++mi) {
            int row = m0 + mi * 16 + (lane >> 2);
            float2 v0 = {acc[mi][ni][0] + bv.x, acc[mi][ni][1] + bv.y};
            float2 v1 = {acc[mi][ni][2] + bv.x, acc[mi][ni][3] + bv.y};
            if (MODE == 0) {
                *reinterpret_cast<float2*>(C + (size_t)row * ldc + col) = v0;
                *reinterpret_cast<float2*>(C + (size_t)(row + 8) * ldc + col) = v1;
            } else {
                __half hx, lx, hy, ly;
                split1(v0.x, hx, lx); split1(v0.y, hy, ly);
                *reinterpret_cast<__half2*>(Chi + (size_t)row * ldc + col) =
                    __halves2half2(hx, hy);
                *reinterpret_cast<__half2*>(Clo + (size_t)row * ldc + col) =
                    __halves2half2(lx, ly);
                split1(v1.x, hx, lx); split1(v1.y, hy, ly);
                *reinterpret_cast<__half2*>(Chi + (size_t)(row + 8) * ldc + col) =
                    __halves2half2(hx, hy);
                *reinterpret_cast<__half2*>(Clo + (size_t)(row + 8) * ldc + col) =
                    __halves2half2(lx, ly);
            }
        }
    }
}

// ---------------- BIG logits GEMM: 128x128 CTA tile, 128 thr (4 warps of
// 64x64), 3-stage cp.async pipeline. -----------------------------------------
__global__ void __launch_bounds__(128)
k_big(float* __restrict__ C, int ldc,
      const __half* __restrict__ A, const __half* __restrict__ B,
      const float* __restrict__ bias, int K) {
    extern __shared__ char smem[];
    constexpr int TILE_B = 128 * 128;
    constexpr int STG    = 2 * TILE_B;

    const uint32_t sb = smem_u32(smem);
    const int tid    = threadIdx.x;
    const int lane   = tid & 31;
    const int wid    = tid >> 5;
    const int warp_m = wid & 1;
    const int warp_n = wid >> 1;

    const int mBase = blockIdx.y * 128;
    const int nBase = blockIdx.x * 128;
    const int total = K >> 6;

    const int ldr = tid >> 3;
    const int ldg = tid & 7;

    auto load_chunk = [&](int ch) {
        const int st = ch % 3;
        const __half* Ag = A + (size_t)mBase * K + ch * 64;
        const __half* Bg = B + (size_t)nBase * K + ch * 64;
        const uint32_t a_u = sb + st * STG;
        const uint32_t b_u = a_u + TILE_B;
#pragma unroll
        for (int it = 0; it < 8; ++it) {
            int r = ldr + it * 16;
            uint32_t off = (uint32_t)(r * 128 + (ldg * 16 ^ ((r & 7) << 4)));
            cp_async16(a_u + off, Ag + (size_t)r * K + ldg * 8);
            cp_async16(b_u + off, Bg + (size_t)r * K + ldg * 8);
        }
        cp_commit();
    };

    float acc[4][8][4];
#pragma unroll
    for (int mi = 0; mi < 4; ++mi)
#pragma unroll
        for (int ni = 0; ni < 8; ++ni)
#pragma unroll
            for (int q = 0; q < 4; ++q) acc[mi][ni][q] = 0.f;

    int arow[4], brow[4];
#pragma unroll
    for (int mi = 0; mi < 4; ++mi)
        arow[mi] = warp_m * 64 + mi * 16 + (lane & 7) + ((lane >> 3) & 1) * 8;
#pragma unroll
    for (int nq = 0; nq < 4; ++nq)
        brow[nq] = warp_n * 64 + nq * 16 + (lane & 7) + (lane >> 4) * 8;
    const int akb = (lane >> 4) * 16;
    const int bkb = ((lane >> 3) & 1) * 16;

    load_chunk(0);
    load_chunk(1);

    for (int ch = 0; ch < total; ++ch) {
        if (ch + 1 < total) cp_wait<1>(); else cp_wait<0>();
        __syncthreads();
        if (ch + 2 < total) load_chunk(ch + 2);

        const uint32_t a_u = sb + (ch % 3) * STG;
        const uint32_t b_u = a_u + TILE_B;
#pragma unroll
        for (int ks = 0; ks < 4; ++ks) {
            uint32_t aF[4][4];
#pragma unroll
            for (int mi = 0; mi < 4; ++mi) {
                int r = arow[mi], kb = ks * 32 + akb;
                ldsm_x4(aF[mi], a_u + r * 128 + (kb ^ ((r & 7) << 4)));
            }
            uint32_t bF[4][4];
#pragma unroll
            for (int nq = 0; nq < 4; ++nq) {
                int r = brow[nq], kb = ks * 32 + bkb;
                ldsm_x4(bF[nq], b_u + r * 128 + (kb ^ ((r & 7) << 4)));
            }
#pragma unroll
            for (int mi = 0; mi < 4; ++mi)
#pragma unroll
                for (int ni = 0; ni < 8; ++ni)
                    mma16816(acc[mi][ni], aF[mi],
                             bF[ni >> 1][(ni & 1) * 2], bF[ni >> 1][(ni & 1) * 2 + 1]);
        }
    }

    const int m0 = mBase + warp_m * 64;
    const int n0 = nBase + warp_n * 64;
#pragma unroll
    for (int ni = 0; ni < 8; ++ni) {
        int col = n0 + ni * 8 + 2 * (lane & 3);
        float2 bv = *reinterpret_cast<const float2*>(bias + col);
#pragma unroll
        for (int mi = 0; mi < 4; ++mi) {
            int row = m0 + mi * 16 + (lane >> 2);
            float2 v0 = {acc[mi][ni][0] + bv.x, acc[mi][ni][1] + bv.y};
            float2 v1 = {acc[mi][ni][2] + bv.x, acc[mi][ni][3] + bv.y};
            *reinterpret_cast<float2*>(C + (size_t)row * ldc + col) = v0;
            *reinterpret_cast<float2*>(C + (size_t)(row + 8) * ldc + col) = v1;
        }
    }
}

// ---------------- persistent LSTM recurrence, SMEM-resident operands --------
// SMEM: B (Whh slice, 8 chunks x 8KB = 64KB) loaded ONCE; A (h hi+lo, 16
// chunks x 8KB = 128KB) loaded per step in one burst (single wait), then all
// 16 chunks computed back-to-back with no intra-step syncs.
__global__ void __launch_bounds__(128)
k_rec(const __half* __restrict__ Bw, const float* __restrict__ xproj,
      const float* __restrict__ bhhp, float* __restrict__ cst,
      __half* __restrict__ hall) {
    extern __shared__ char smem[];
    constexpr int CH_B   = 64 * 128;        // 8 KB per chunk
    constexpr int A_OFF  = 8 * CH_B;        // B: chunks 0..7 at offset 0

    const uint32_t sb = smem_u32(smem);
    const int tid    = threadIdx.x;
    const int lane   = tid & 31;
    const int wid    = tid >> 5;
    const int warp_m = wid & 1;
    const int warp_n = wid >> 1;

    const int mBase = blockIdx.y * 64;
    const int nBase = blockIdx.x * 64;

    const int ldr = tid >> 3;   // 0..15
    const int ldg = tid & 7;

    int arow[2], brow[2];
#pragma unroll
    for (int mi = 0; mi < 2; ++mi)
        arow[mi] = warp_m * 32 + mi * 16 + (lane & 7) + ((lane >> 3) & 1) * 8;
#pragma unroll
    for (int nq = 0; nq < 2; ++nq)
        brow[nq] = warp_n * 32 + nq * 16 + (lane & 7) + (lane >> 4) * 8;
    const int akb = (lane >> 4) * 16;
    const int bkb = ((lane >> 3) & 1) * 16;

    // ---- load B (Whh slice) once: 8 chunks ----
#pragma unroll
    for (int kc = 0; kc < 8; ++kc) {
        const __half* Bg = Bw + (size_t)nBase * HD + kc * 64;
        const uint32_t b_u = sb + kc * CH_B;
#pragma unroll
        for (int it = 0; it < 4; ++it) {
            int r = ldr + it * 16;
            uint32_t off = (uint32_t)(r * 128 + (ldg * 16 ^ ((r & 7) << 4)));
            cp_async16(b_u + off, Bg + (size_t)r * HD + ldg * 8);
        }
    }
    cp_commit();

    for (int t = 0; t < TT; ++t) {
        float acc[2][4][4];
#pragma unroll
        for (int mi = 0; mi < 2; ++mi)
#pragma unroll
            for (int ni = 0; ni < 4; ++ni)
#pragma unroll
                for (int q = 0; q < 4; ++q) acc[mi][ni][q] = 0.f;

        if (t > 0) {
            const int rd = t & 1;
            const __half* Ap[2] = {d_h_hi[rd], d_h_lo[rd]};

            // ---- burst-load ALL of A (2 passes x 8 chunks) ----
#pragma unroll
            for (int ch = 0; ch < 16; ++ch) {
                const int pass = ch >> 3;
                const int kc   = ch & 7;
                const __half* Ag = Ap[pass] + (size_t)mBase * HD + kc * 64;
                const uint32_t a_u = sb + A_OFF + ch * CH_B;
#pragma unroll
                for (int it = 0; it < 4; ++it) {
                    int r = ldr + it * 16;
                    uint32_t off = (uint32_t)(r * 128 + (ldg * 16 ^ ((r & 7) << 4)));
                    cp_async16(a_u + off, Ag + (size_t)r * HD + ldg * 8);
                }
            }
            cp_commit();
            cp_wait<0>();      // also covers the B load on the first step
            __syncthreads();

            // ---- compute all 16 chunks, no further syncs ----
            for (int ch = 0; ch < 16; ++ch) {
                const uint32_t a_u = sb + A_OFF + ch * CH_B;
                const uint32_t b_u = sb + (ch & 7) * CH_B;
#pragma unroll
                for (int ks = 0; ks < 4; ++ks) {
                    uint32_t aF[2][4];
#pragma unroll
                    for (int mi = 0; mi < 2; ++mi) {
                        int r = arow[mi], kb = ks * 32 + akb;
                        ldsm_x4(aF[mi], a_u + r * 128 + (kb ^ ((r & 7) << 4)));
                    }
                    uint32_t bF[2][4];
#pragma unroll
                    for (int nq = 0; nq < 2; ++nq) {
                        int r = brow[nq], kb = ks * 32 + bkb;
                        ldsm_x4(bF[nq], b_u + r * 128 + (kb ^ ((r & 7) << 4)));
                    }
#pragma unroll
                    for (int mi = 0; mi < 2; ++mi)
#pragma unroll
                        for (int ni = 0; ni < 4; ++ni)
                            mma16816(acc[mi][ni], aF[mi],
                                     bF[ni >> 1][(ni & 1) * 2], bF[ni >> 1][(ni & 1) * 2 + 1]);
                }
            }
            __syncthreads();   // A buffer reused next step after barrier
        }

        // ---- cell epilogue: write h into buffer (t+1)&1 ----
        {
            const int wr = (t + 1) & 1;
            __half* hhi = d_h_hi[wr];
            __half* hlo = d_h_lo[wr];
            const int m0  = mBase + warp_m * 32;
            const int n0g = nBase + warp_n * 32;
            const int a   = lane & 3;
            const int rb  = lane >> 2;
#pragma unroll
            for (int ni = 0; ni < 4; ++ni) {
                int col = n0g + ni * 8 + 2 * a;
                float2 bb = *reinterpret_cast<const float2*>(bhhp + col);
#pragma unroll
                for (int mi = 0; mi < 2; ++mi) {
#pragma unroll
                    for (int hq = 0; hq < 2; ++hq) {
                        int row = m0 + mi * 16 + rb + hq * 8;
                        float2 xp = *reinterpret_cast<const float2*>(
                            xproj + (size_t)row * G4 + col);
                        float g0 = acc[mi][ni][hq * 2 + 0] + xp.x + bb.x;
                        float g1 = acc[mi][ni][hq * 2 + 1] + xp.y + bb.y;
                        float o0 = __shfl_xor_sync(0xFFFFFFFFu, g0, 1);
                        float o1 = __shfl_xor_sync(0xFFFFFFFFu, g1, 1);
                        if ((a & 1) == 0) {
                            float si = 1.f / (1.f + expf(-g0));
                            float sf = 1.f / (1.f + expf(-g1));
                            float tg = tanhf(o0);
                            float so = 1.f / (1.f + expf(-o1));
                            int j = (n0g >> 2) + 2 * ni + (a >> 1);
                            float cp = (t == 0) ? 0.f : cst[(size_t)row * HD + j];
                            float cn = sf * cp + si * tg;
                            cst[(size_t)row * HD + j] = cn;
                            float h = so * tanhf(cn);
                            __half hh = __float2half_rn(h);
                            hhi[(size_t)row * HD + j] = hh;
                            hlo[(size_t)row * HD + j] = __float2half_rn(h - __half2float(hh));
                            hall[((size_t)row * TT + t) * HD + j] = hh;
                        }
                    }
                }
            }
        }

        if (t + 1 < TT) grid_barrier();
    }
}

// ---------------- host orchestration ----------------
extern "C" void kernel_launch(void* const* d_in, const int* in_sizes, int n_in,
                              void* d_out, int out_size) {
    const float* context = (const float*)d_in[0];
    const float* W_merge = (const float*)d_in[1];
    const float* b_merge = (const float*)d_in[2];
    const float* W_ih    = (const float*)d_in[3];
    const float* W_hh    = (const float*)d_in[4];
    const float* b_ih    = (const float*)d_in[5];
    const float* b_hh    = (const float*)d_in[6];
    const float* W_out   = (const float*)d_in[7];
    const float* b_out   = (const float*)d_in[8];
    float* out = (float*)d_out;

    __half *ctxin_hi, *ctxin_lo, *wm_hi, *wm_lo, *wih_hi, *wih_lo, *whhp, *wo16;
    __half *ctx_hi, *ctx_lo, *hall;
    float *xproj, *cbuf, *bihp, *bhhp;
    cudaGetSymbolAddress((void**)&ctxin_hi, d_ctxin_hi);
    cudaGetSymbolAddress((void**)&ctxin_lo, d_ctxin_lo);
    cudaGetSymbolAddress((void**)&wm_hi, d_wm_hi);
    cudaGetSymbolAddress((void**)&wm_lo, d_wm_lo);
    cudaGetSymbolAddress((void**)&wih_hi, d_wih_hi);
    cudaGetSymbolAddress((void**)&wih_lo, d_wih_lo);
    cudaGetSymbolAddress((void**)&whhp, d_whhp);
    cudaGetSymbolAddress((void**)&wo16, d_wo16);
    cudaGetSymbolAddress((void**)&bihp, d_bihp);
    cudaGetSymbolAddress((void**)&bhhp, d_bhhp);
    cudaGetSymbolAddress((void**)&ctx_hi, d_ctx_hi);
    cudaGetSymbolAddress((void**)&ctx_lo, d_ctx_lo);
    cudaGetSymbolAddress((void**)&xproj, d_xproj);
    cudaGetSymbolAddress((void**)&cbuf, d_cst);
    cudaGetSymbolAddress((void**)&hall, d_hall);

    const int SMEM64  = 3 * 2 * 64 * 128;    // 49152
    const int SMEMBIG = 3 * 2 * 128 * 128;   // 98304
    const int SMEMREC = 24 * 64 * 128;       // 196608 (8 B-chunks + 16 A-chunks)
    cudaFuncSetAttribute(k_g64<3, 0>, cudaFuncAttributeMaxDynamicSharedMemorySize, SMEM64);
    cudaFuncSetAttribute(k_g64<3, 2>, cudaFuncAttributeMaxDynamicSharedMemorySize, SMEM64);
    cudaFuncSetAttribute(k_rec, cudaFuncAttributeMaxDynamicSharedMemorySize, SMEMREC);
    cudaFuncSetAttribute(k_big, cudaFuncAttributeMaxDynamicSharedMemorySize, SMEMBIG);

    // launch 0: merged conversion + permutation
    k_prep<<<2048, 256>>>((const float4*)context, (const float4*)W_merge,
                          W_ih, W_hh, (const float4*)W_out, b_ih, b_hh);

    // launch 1: GEMM1  ctx = context @ Wm^T + b_merge (3-pass), split-store
    {
        dim3 g(HD / 64, NB / 64);  // (8,4)
        k_g64<3, 2><<<g, 128, SMEM64>>>(nullptr, ctx_hi, ctx_lo, HD,
            ctxin_hi, ctxin_lo, ctxin_hi,
            wm_hi, wm_hi, wm_lo,
            b_merge, CAT);
    }
    // launch 2: GEMM2  x_proj(perm) = ctx @ Wih_p^T + b_ih_p (3-pass)
    {
        dim3 g(G4 / 64, NB / 64);  // (32,4)
        k_g64<3, 0><<<g, 128, SMEM64>>>(xproj, nullptr, nullptr, G4,
            ctx_hi, ctx_lo, ctx_hi,
            wih_hi, wih_hi, wih_lo,
            bihp, HD);
    }
    // launch 3: persistent LSTM recurrence (all TT steps)
    {
        dim3 g(G4 / 64, NB / 64);  // (32,4) = 128 CTAs
        k_rec<<<g, 128, SMEMREC>>>(whhp, xproj, bhhp, cbuf, hall);
    }
    // launch 4: big GEMM  out[2048,32000] = H_all @ Wo^T + b_out
    {
        dim3 g(VOC / 128, (NB * TT) / 128);  // (250,16)
        k_big<<<g, 128, SMEMBIG>>>(out, VOC, hall, wo16, b_out, HD);
    }
}

// round 8
// speedup vs baseline: 1.5547x; 1.1999x over previous
#include <cuda_runtime.h>
#include <cuda_fp16.h>
#include <cstdint>
#include <cstddef>

#define DI __device__ __forceinline__

static constexpr int NB  = 256;     // batch
static constexpr int CAT = 1024;
static constexpr int HD  = 512;
static constexpr int VOC = 32000;
static constexpr int TT  = 8;
static constexpr int G4  = 4 * HD;  // 2048
static constexpr int REC_CTAS = (G4 / 64) * (NB / 64);  // 128

// ---------------- device scratch (static: no allocation) ----------------
__device__ __half d_ctxin_hi[NB * CAT];
__device__ __half d_ctxin_lo[NB * CAT];
__device__ __half d_wm_hi[HD * CAT];
__device__ __half d_wm_lo[HD * CAT];
__device__ __half d_wih_hi[G4 * HD];   // gate-interleaved rows
__device__ __half d_wih_lo[G4 * HD];   // gate-interleaved rows
__device__ __half d_whhp[G4 * HD];     // gate-interleaved rows
__device__ __half d_wo16[VOC * HD];
__device__ float  d_bihp[G4];          // permuted b_ih
__device__ float  d_bhhp[G4];          // permuted b_hh
__device__ __half d_ctx_hi[NB * HD];
__device__ __half d_ctx_lo[NB * HD];
__device__ float  d_xproj[NB * G4];    // gate-interleaved cols
__device__ __half d_h_hi[2][NB * HD];  // double-buffered across steps
__device__ __half d_h_lo[2][NB * HD];
__device__ __half d_hall[NB * TT * HD];
__device__ unsigned d_bar_cnt = 0;
__device__ unsigned d_bar_gen = 0;

// ---------------- PTX helpers ----------------
DI uint32_t smem_u32(const void* p) {
    uint32_t a;
    asm("{ .reg .u64 t; cvta.to.shared.u64 t, %1; cvt.u32.u64 %0, t; }"
        : "=r"(a) : "l"(p));
    return a;
}
DI void cp_async16(uint32_t dst, const void* src) {
    asm volatile("cp.async.cg.shared.global [%0], [%1], 16;"
                 :: "r"(dst), "l"(src) : "memory");
}
DI void cp_commit() { asm volatile("cp.async.commit_group;" ::: "memory"); }
template <int N>
DI void cp_wait() { asm volatile("cp.async.wait_group %0;" :: "n"(N) : "memory"); }

DI void ldsm_x4(uint32_t (&d)[4], uint32_t addr) {
    asm volatile("ldmatrix.sync.aligned.m8n8.x4.shared.b16 {%0,%1,%2,%3}, [%4];"
                 : "=r"(d[0]), "=r"(d[1]), "=r"(d[2]), "=r"(d[3]) : "r"(addr));
}
DI void mma16816(float (&c)[4], const uint32_t (&a)[4], uint32_t b0, uint32_t b1) {
    asm volatile(
        "mma.sync.aligned.m16n8k16.row.col.f32.f16.f16.f32 "
        "{%0,%1,%2,%3}, {%4,%5,%6,%7}, {%8,%9}, {%0,%1,%2,%3};"
        : "+f"(c[0]), "+f"(c[1]), "+f"(c[2]), "+f"(c[3])
        : "r"(a[0]), "r"(a[1]), "r"(a[2]), "r"(a[3]), "r"(b0), "r"(b1));
}

DI void split1(float v, __half& hi, __half& lo) {
    __half h = __float2half_rn(v);
    hi = h;
    lo = __float2half_rn(v - __half2float(h));
}
DI void split4(float4 v, __half2* hi2, __half2* lo2) {
    __half2 h01 = __floats2half2_rn(v.x, v.y);
    __half2 h23 = __floats2half2_rn(v.z, v.w);
    float2 f01 = __half22float2(h01);
    float2 f23 = __half22float2(h23);
    hi2[0] = h01; hi2[1] = h23;
    lo2[0] = __floats2half2_rn(v.x - f01.x, v.y - f01.y);
    lo2[1] = __floats2half2_rn(v.z - f23.x, v.w - f23.y);
}

// device-wide sense barrier (all REC_CTAS CTAs co-resident)
DI void grid_barrier() {
    __syncthreads();
    if (threadIdx.x == 0) {
        __threadfence();
        unsigned g;
        asm volatile("ld.acquire.gpu.global.u32 %0, [%1];"
                     : "=r"(g) : "l"(&d_bar_gen));
        unsigned v = atomicAdd(&d_bar_cnt, 1u);
        if (v == REC_CTAS - 1) {
            d_bar_cnt = 0;
            asm volatile("red.release.gpu.global.add.u32 [%0], 1;"
                         :: "l"(&d_bar_gen) : "memory");
        } else {
            unsigned cur;
            do {
                asm volatile("ld.acquire.gpu.global.u32 %0, [%1];"
                             : "=r"(cur) : "l"(&d_bar_gen));
            } while (cur == g);
        }
    }
    __syncthreads();
}

// ---------------- merged conversion / permutation kernel ----------------
__global__ void k_prep(const float4* __restrict__ ctx, const float4* __restrict__ wm,
                       const float* __restrict__ wih, const float* __restrict__ whh,
                       const float4* __restrict__ wo,
                       const float* __restrict__ bih, const float* __restrict__ bhh) {
    constexpr int R0 = NB * CAT / 4;
    constexpr int R1 = R0 + HD * CAT / 4;
    constexpr int R2 = R1 + G4 * HD / 4;
    constexpr int R3 = R2 + G4 * HD / 4;
    constexpr int R4 = R3 + VOC * HD / 4;
    constexpr int HD4 = HD / 4;

    if (blockIdx.x == 0) {
        for (int p = threadIdx.x; p < G4; p += blockDim.x) {
            int j = p >> 2, q = p & 3;
            d_bihp[p] = bih[q * HD + j];
            d_bhhp[p] = bhh[q * HD + j];
        }
    }
    int stride = gridDim.x * blockDim.x;
    for (int u = blockIdx.x * blockDim.x + threadIdx.x; u < R4; u += stride) {
        if (u < R0) {
            split4(ctx[u], (__half2*)d_ctxin_hi + 2 * u, (__half2*)d_ctxin_lo + 2 * u);
        } else if (u < R1) {
            int v = u - R0;
            split4(wm[v], (__half2*)d_wm_hi + 2 * v, (__half2*)d_wm_lo + 2 * v);
        } else if (u < R2) {
            int v = u - R1;
            int p = v >> 7, c4 = v & (HD4 - 1);
            int j = p >> 2, q = p & 3;
            float4 w = *reinterpret_cast<const float4*>(wih + (size_t)(q * HD + j) * HD + c4 * 4);
            split4(w, (__half2*)d_wih_hi + 2 * v, (__half2*)d_wih_lo + 2 * v);
        } else if (u < R3) {
            int v = u - R2;
            int p = v >> 7, c4 = v & (HD4 - 1);
            int j = p >> 2, q = p & 3;
            float4 w = *reinterpret_cast<const float4*>(whh + (size_t)(q * HD + j) * HD + c4 * 4);
            __half2* o = (__half2*)d_whhp + 2 * v;
            o[0] = __floats2half2_rn(w.x, w.y);
            o[1] = __floats2half2_rn(w.z, w.w);
        } else {
            int v = u - R3;
            float4 w = wo[v];
            __half2* o = (__half2*)d_wo16 + 2 * v;
            o[0] = __floats2half2_rn(w.x, w.y);
            o[1] = __floats2half2_rn(w.z, w.w);
        }
    }
}

// ---------------- 64x64 HMMA GEMM, 128 thr, 3-stage -------------------------
// MODE 0: C = acc + bias (fp32). MODE 2: split-fp16 store to Chi/Clo.
template <int NPASS, int MODE>
__global__ void __launch_bounds__(128)
k_g64(float* __restrict__ C, __half* __restrict__ Chi, __half* __restrict__ Clo,
      int ldc,
      const __half* __restrict__ A0, const __half* __restrict__ A1,
      const __half* __restrict__ A2,
      const __half* __restrict__ B0, const __half* __restrict__ B1,
      const __half* __restrict__ B2,
      const float* __restrict__ bias, int K) {
    extern __shared__ char smem[];
    constexpr int TILE_B = 64 * 128;
    constexpr int STG    = 2 * TILE_B;

    const uint32_t sb = smem_u32(smem);
    const int tid    = threadIdx.x;
    const int lane   = tid & 31;
    const int wid    = tid >> 5;
    const int warp_m = wid & 1;
    const int warp_n = wid >> 1;

    const int mBase = blockIdx.y * 64;
    const int nBase = blockIdx.x * 64;

    const __half* Ap[3] = {A0, A1, A2};
    const __half* Bp[3] = {B0, B1, B2};
    const int kch   = K >> 6;
    const int total = NPASS * kch;

    const int ldr = tid >> 3;
    const int ldg = tid & 7;

    auto load_chunk = [&](int ch) {
        const int st   = ch % 3;
        const int pass = ch / kch;
        const int kc   = ch - pass * kch;
        const __half* Ag = Ap[pass] + (size_t)mBase * K + kc * 64;
        const __half* Bg = Bp[pass] + (size_t)nBase * K + kc * 64;
        const uint32_t a_u = sb + st * STG;
        const uint32_t b_u = a_u + TILE_B;
#pragma unroll
        for (int it = 0; it < 4; ++it) {
            int r = ldr + it * 16;
            uint32_t off = (uint32_t)(r * 128 + (ldg * 16 ^ ((r & 7) << 4)));
            cp_async16(a_u + off, Ag + (size_t)r * K + ldg * 8);
            cp_async16(b_u + off, Bg + (size_t)r * K + ldg * 8);
        }
        cp_commit();
    };

    float acc[2][4][4];
#pragma unroll
    for (int mi = 0; mi < 2; ++mi)
#pragma unroll
        for (int ni = 0; ni < 4; ++ni)
#pragma unroll
            for (int q = 0; q < 4; ++q) acc[mi][ni][q] = 0.f;

    int arow[2], brow[2];
#pragma unroll
    for (int mi = 0; mi < 2; ++mi)
        arow[mi] = warp_m * 32 + mi * 16 + (lane & 7) + ((lane >> 3) & 1) * 8;
#pragma unroll
    for (int nq = 0; nq < 2; ++nq)
        brow[nq] = warp_n * 32 + nq * 16 + (lane & 7) + (lane >> 4) * 8;
    const int akb = (lane >> 4) * 16;
    const int bkb = ((lane >> 3) & 1) * 16;

    load_chunk(0);
    load_chunk(1);
    for (int ch = 0; ch < total; ++ch) {
        if (ch + 1 < total) cp_wait<1>(); else cp_wait<0>();
        __syncthreads();
        if (ch + 2 < total) load_chunk(ch + 2);

        const uint32_t a_u = sb + (ch % 3) * STG;
        const uint32_t b_u = a_u + TILE_B;
#pragma unroll
        for (int ks = 0; ks < 4; ++ks) {
            uint32_t aF[2][4];
#pragma unroll
            for (int mi = 0; mi < 2; ++mi) {
                int r = arow[mi], kb = ks * 32 + akb;
                ldsm_x4(aF[mi], a_u + r * 128 + (kb ^ ((r & 7) << 4)));
            }
            uint32_t bF[2][4];
#pragma unroll
            for (int nq = 0; nq < 2; ++nq) {
                int r = brow[nq], kb = ks * 32 + bkb;
                ldsm_x4(bF[nq], b_u + r * 128 + (kb ^ ((r & 7) << 4)));
            }
#pragma unroll
            for (int mi = 0; mi < 2; ++mi)
#pragma unroll
                for (int ni = 0; ni < 4; ++ni)
                    mma16816(acc[mi][ni], aF[mi],
                             bF[ni >> 1][(ni & 1) * 2], bF[ni >> 1][(ni & 1) * 2 + 1]);
        }
    }

    const int m0 = mBase + warp_m * 32;
    const int n0 = nBase + warp_n * 32;
#pragma unroll
    for (int ni = 0; ni < 4; ++ni) {
        int col = n0 + ni * 8 + 2 * (lane & 3);
        float2 bv = *reinterpret_cast<const float2*>(bias + col);
#pragma unroll
        for (int mi = 0; mi < 2; ++mi) {
            int row = m0 + mi * 16 + (lane >> 2);
            float2 v0 = {acc[mi][ni][0] + bv.x, acc[mi][ni][1] + bv.y};
            float2 v1 = {acc[mi][ni][2] + bv.x, acc[mi][ni][3] + bv.y};
            if (MODE == 0) {
                *reinterpret_cast<float2*>(C + (size_t)row * ldc + col) = v0;
                *reinterpret_cast<float2*>(C + (size_t)(row + 8) * ldc + col) = v1;
            } else {
                __half hx, lx, hy, ly;
                split1(v0.x, hx, lx); split1(v0.y, hy, ly);
                *reinterpret_cast<__half2*>(Chi + (size_t)row * ldc + col) =
                    __halves2half2(hx, hy);
                *reinterpret_cast<__half2*>(Clo + (size_t)row * ldc + col) =
                    __halves2half2(lx, ly);
                split1(v1.x, hx, lx); split1(v1.y, hy, ly);
                *reinterpret_cast<__half2*>(Chi + (size_t)(row + 8) * ldc + col) =
                    __halves2half2(hx, hy);
                *reinterpret_cast<__half2*>(Clo + (size_t)(row + 8) * ldc + col) =
                    __halves2half2(lx, ly);
            }
        }
    }
}

// ---------------- BIG logits GEMM: 128x128 CTA tile, 128 thr (4 warps of
// 64x64), 3-stage cp.async pipeline. -----------------------------------------
__global__ void __launch_bounds__(128)
k_big(float* __restrict__ C, int ldc,
      const __half* __restrict__ A, const __half* __restrict__ B,
      const float* __restrict__ bias, int K) {
    extern __shared__ char smem[];
    constexpr int TILE_B = 128 * 128;
    constexpr int STG    = 2 * TILE_B;

    const uint32_t sb = smem_u32(smem);
    const int tid    = threadIdx.x;
    const int lane   = tid & 31;
    const int wid    = tid >> 5;
    const int warp_m = wid & 1;
    const int warp_n = wid >> 1;

    const int mBase = blockIdx.y * 128;
    const int nBase = blockIdx.x * 128;
    const int total = K >> 6;

    const int ldr = tid >> 3;
    const int ldg = tid & 7;

    auto load_chunk = [&](int ch) {
        const int st = ch % 3;
        const __half* Ag = A + (size_t)mBase * K + ch * 64;
        const __half* Bg = B + (size_t)nBase * K + ch * 64;
        const uint32_t a_u = sb + st * STG;
        const uint32_t b_u = a_u + TILE_B;
#pragma unroll
        for (int it = 0; it < 8; ++it) {
            int r = ldr + it * 16;
            uint32_t off = (uint32_t)(r * 128 + (ldg * 16 ^ ((r & 7) << 4)));
            cp_async16(a_u + off, Ag + (size_t)r * K + ldg * 8);
            cp_async16(b_u + off, Bg + (size_t)r * K + ldg * 8);
        }
        cp_commit();
    };

    float acc[4][8][4];
#pragma unroll
    for (int mi = 0; mi < 4; ++mi)
#pragma unroll
        for (int ni = 0; ni < 8; ++ni)
#pragma unroll
            for (int q = 0; q < 4; ++q) acc[mi][ni][q] = 0.f;

    int arow[4], brow[4];
#pragma unroll
    for (int mi = 0; mi < 4; ++mi)
        arow[mi] = warp_m * 64 + mi * 16 + (lane & 7) + ((lane >> 3) & 1) * 8;
#pragma unroll
    for (int nq = 0; nq < 4; ++nq)
        brow[nq] = warp_n * 64 + nq * 16 + (lane & 7) + (lane >> 4) * 8;
    const int akb = (lane >> 4) * 16;
    const int bkb = ((lane >> 3) & 1) * 16;

    load_chunk(0);
    load_chunk(1);

    for (int ch = 0; ch < total; ++ch) {
        if (ch + 1 < total) cp_wait<1>(); else cp_wait<0>();
        __syncthreads();
        if (ch + 2 < total) load_chunk(ch + 2);

        const uint32_t a_u = sb + (ch % 3) * STG;
        const uint32_t b_u = a_u + TILE_B;
#pragma unroll
        for (int ks = 0; ks < 4; ++ks) {
            uint32_t aF[4][4];
#pragma unroll
            for (int mi = 0; mi < 4; ++mi) {
                int r = arow[mi], kb = ks * 32 + akb;
                ldsm_x4(aF[mi], a_u + r * 128 + (kb ^ ((r & 7) << 4)));
            }
            uint32_t bF[4][4];
#pragma unroll
            for (int nq = 0; nq < 4; ++nq) {
                int r = brow[nq], kb = ks * 32 + bkb;
                ldsm_x4(bF[nq], b_u + r * 128 + (kb ^ ((r & 7) << 4)));
            }
#pragma unroll
            for (int mi = 0; mi < 4; ++mi)
#pragma unroll
                for (int ni = 0; ni < 8; ++ni)
                    mma16816(acc[mi][ni], aF[mi],
                             bF[ni >> 1][(ni & 1) * 2], bF[ni >> 1][(ni & 1) * 2 + 1]);
        }
    }

    const int m0 = mBase + warp_m * 64;
    const int n0 = nBase + warp_n * 64;
#pragma unroll
    for (int ni = 0; ni < 8; ++ni) {
        int col = n0 + ni * 8 + 2 * (lane & 3);
        float2 bv = *reinterpret_cast<const float2*>(bias + col);
#pragma unroll
        for (int mi = 0; mi < 4; ++mi) {
            int row = m0 + mi * 16 + (lane >> 2);
            float2 v0 = {acc[mi][ni][0] + bv.x, acc[mi][ni][1] + bv.y};
            float2 v1 = {acc[mi][ni][2] + bv.x, acc[mi][ni][3] + bv.y};
            *reinterpret_cast<float2*>(C + (size_t)row * ldc + col) = v0;
            *reinterpret_cast<float2*>(C + (size_t)(row + 8) * ldc + col) = v1;
        }
    }
}

// ---------------- persistent LSTM recurrence, 256 threads -------------------
// SMEM: B (Whh slice, 64KB) + xproj tile (16KB) loaded once; A (h hi+lo,
// 128KB) burst-loaded per step. Warp grid 2(M)x4(N), warp tile 32x16.
// c-state in registers; h/hall staged in SMEM then flushed coalesced.
__global__ void __launch_bounds__(256)
k_rec(const __half* __restrict__ Bw, const float* __restrict__ xproj,
      const float* __restrict__ bhhp, __half* __restrict__ hall) {
    extern __shared__ char smem[];
    constexpr int CH_B   = 64 * 128;       // 8 KB per chunk
    constexpr int A_OFF  = 8 * CH_B;       // 64 KB: B chunks 0..7
    constexpr int XP_OFF = 24 * CH_B;      // 192 KB: xproj tile (16 KB)
    constexpr int ST_HI  = A_OFF;          // staging reuses A region
    constexpr int ST_LO  = A_OFF + 2048;

    const uint32_t sb = smem_u32(smem);
    const int tid    = threadIdx.x;
    const int lane   = tid & 31;
    const int wid    = tid >> 5;
    const int warp_m = wid & 1;    // 2 M-slices of 32
    const int warp_n = wid >> 1;   // 4 N-slices of 16

    const int mBase = blockIdx.y * 64;
    const int nBase = blockIdx.x * 64;

    const int ldr = tid >> 3;      // 0..31
    const int ldg = tid & 7;

    int arow[2];
#pragma unroll
    for (int mi = 0; mi < 2; ++mi)
        arow[mi] = warp_m * 32 + mi * 16 + (lane & 7) + ((lane >> 3) & 1) * 8;
    const int brow = warp_n * 16 + (lane & 7) + (lane >> 4) * 8;
    const int akb  = (lane >> 4) * 16;
    const int bkb  = ((lane >> 3) & 1) * 16;

    // ---- load B (Whh slice) + xproj tile once ----
#pragma unroll
    for (int kc = 0; kc < 8; ++kc) {
        const __half* Bg = Bw + (size_t)nBase * HD + kc * 64;
        const uint32_t b_u = sb + kc * CH_B;
#pragma unroll
        for (int it = 0; it < 2; ++it) {
            int r = ldr + it * 32;
            uint32_t off = (uint32_t)(r * 128 + (ldg * 16 ^ ((r & 7) << 4)));
            cp_async16(b_u + off, Bg + (size_t)r * HD + ldg * 8);
        }
    }
#pragma unroll
    for (int i = tid; i < 64 * 16; i += 256) {  // 1024 float4
        int row = i >> 4, c4 = i & 15;
        cp_async16(sb + XP_OFF + (uint32_t)(row * 64 + c4 * 4) * 4,
                   xproj + (size_t)(mBase + row) * G4 + nBase + c4 * 4);
    }
    cp_commit();
    cp_wait<0>();
    __syncthreads();

    float creg[2][2][2];  // c-state (mi, ni, hq) — valid on even-a lanes

    for (int t = 0; t < TT; ++t) {
        float acc[2][2][4];
#pragma unroll
        for (int mi = 0; mi < 2; ++mi)
#pragma unroll
            for (int ni = 0; ni < 2; ++ni)
#pragma unroll
                for (int q = 0; q < 4; ++q) acc[mi][ni][q] = 0.f;

        if (t > 0) {
            const int rd = t & 1;
            const __half* Ap[2] = {d_h_hi[rd], d_h_lo[rd]};

            // burst-load ALL of A (2 passes x 8 chunks)
#pragma unroll
            for (int ch = 0; ch < 16; ++ch) {
                const int pass = ch >> 3;
                const int kc   = ch & 7;
                const __half* Ag = Ap[pass] + (size_t)mBase * HD + kc * 64;
                const uint32_t a_u = sb + A_OFF + ch * CH_B;
#pragma unroll
                for (int it = 0; it < 2; ++it) {
                    int r = ldr + it * 32;
                    uint32_t off = (uint32_t)(r * 128 + (ldg * 16 ^ ((r & 7) << 4)));
                    cp_async16(a_u + off, Ag + (size_t)r * HD + ldg * 8);
                }
            }
            cp_commit();
            cp_wait<0>();
            __syncthreads();

            // compute all 16 chunks, no intra-loop syncs
            for (int ch = 0; ch < 16; ++ch) {
                const uint32_t a_u = sb + A_OFF + ch * CH_B;
                const uint32_t b_u = sb + (ch & 7) * CH_B;
#pragma unroll
                for (int ks = 0; ks < 4; ++ks) {
                    uint32_t aF[2][4];
#pragma unroll
                    for (int mi = 0; mi < 2; ++mi) {
                        int r = arow[mi], kb = ks * 32 + akb;
                        ldsm_x4(aF[mi], a_u + r * 128 + (kb ^ ((r & 7) << 4)));
                    }
                    uint32_t bF[4];
                    {
                        int kb = ks * 32 + bkb;
                        ldsm_x4(bF, b_u + brow * 128 + (kb ^ ((brow & 7) << 4)));
                    }
#pragma unroll
                    for (int mi = 0; mi < 2; ++mi)
#pragma unroll
                        for (int ni = 0; ni < 2; ++ni)
                            mma16816(acc[mi][ni], aF[mi], bF[ni * 2], bF[ni * 2 + 1]);
                }
            }
            __syncthreads();   // all LDSM of A done before staging overwrites it
        }

        // ---- cell epilogue: compute h, stage hi/lo into SMEM ----
        {
            const int a  = lane & 3;
            const int rb = lane >> 2;
#pragma unroll
            for (int ni = 0; ni < 2; ++ni) {
                int colL = warp_n * 16 + ni * 8 + 2 * a;   // local gate col 0..63
                float2 bb = *reinterpret_cast<const float2*>(bhhp + nBase + colL);
#pragma unroll
                for (int mi = 0; mi < 2; ++mi) {
#pragma unroll
                    for (int hq = 0; hq < 2; ++hq) {
                        int srow = warp_m * 32 + mi * 16 + rb + hq * 8;  // 0..63
                        float2 xp = *reinterpret_cast<const float2*>(
                            smem + XP_OFF + (srow * 64 + colL) * 4);
                        float g0 = acc[mi][ni][hq * 2 + 0] + xp.x + bb.x;
                        float g1 = acc[mi][ni][hq * 2 + 1] + xp.y + bb.y;
                        float o0 = __shfl_xor_sync(0xFFFFFFFFu, g0, 1);
                        float o1 = __shfl_xor_sync(0xFFFFFFFFu, g1, 1);
                        if ((a & 1) == 0) {
                            float si = 1.f / (1.f + expf(-g0));
                            float sf = 1.f / (1.f + expf(-g1));
                            float tg = tanhf(o0);
                            float so = 1.f / (1.f + expf(-o1));
                            float cp = (t == 0) ? 0.f : creg[mi][ni][hq];
                            float cn = sf * cp + si * tg;
                            creg[mi][ni][hq] = cn;
                            float h = so * tanhf(cn);
                            __half hh, hl;
                            split1(h, hh, hl);
                            int sj = warp_n * 4 + 2 * ni + (a >> 1);     // 0..15
                            *reinterpret_cast<__half*>(smem + ST_HI + (srow * 16 + sj) * 2) = hh;
                            *reinterpret_cast<__half*>(smem + ST_LO + (srow * 16 + sj) * 2) = hl;
                        }
                    }
                }
            }
        }
        __syncthreads();

        // ---- coalesced flush: 64 rows x 16 halfs per array ----
        {
            const int wr = (t + 1) & 1;
            int row  = tid >> 2;        // 0..63
            int part = tid & 3;         // 0..3 (4 halfs each)
            int n  = mBase + row;
            int jg = (nBase >> 2) + part * 4;
            uint2 vhi = *reinterpret_cast<uint2*>(smem + ST_HI + (row * 16 + part * 4) * 2);
            uint2 vlo = *reinterpret_cast<uint2*>(smem + ST_LO + (row * 16 + part * 4) * 2);
            *reinterpret_cast<uint2*>(&d_h_hi[wr][(size_t)n * HD + jg]) = vhi;
            *reinterpret_cast<uint2*>(&d_h_lo[wr][(size_t)n * HD + jg]) = vlo;
            *reinterpret_cast<uint2*>(&hall[((size_t)n * TT + t) * HD + jg]) = vhi;
        }

        if (t + 1 < TT) grid_barrier();
    }
}

// ---------------- host orchestration ----------------
extern "C" void kernel_launch(void* const* d_in, const int* in_sizes, int n_in,
                              void* d_out, int out_size) {
    const float* context = (const float*)d_in[0];
    const float* W_merge = (const float*)d_in[1];
    const float* b_merge = (const float*)d_in[2];
    const float* W_ih    = (const float*)d_in[3];
    const float* W_hh    = (const float*)d_in[4];
    const float* b_ih    = (const float*)d_in[5];
    const float* b_hh    = (const float*)d_in[6];
    const float* W_out   = (const float*)d_in[7];
    const float* b_out   = (const float*)d_in[8];
    float* out = (float*)d_out;

    __half *ctxin_hi, *ctxin_lo, *wm_hi, *wm_lo, *wih_hi, *wih_lo, *whhp, *wo16;
    __half *ctx_hi, *ctx_lo, *hall;
    float *xproj, *bihp, *bhhp;
    cudaGetSymbolAddress((void**)&ctxin_hi, d_ctxin_hi);
    cudaGetSymbolAddress((void**)&ctxin_lo, d_ctxin_lo);
    cudaGetSymbolAddress((void**)&wm_hi, d_wm_hi);
    cudaGetSymbolAddress((void**)&wm_lo, d_wm_lo);
    cudaGetSymbolAddress((void**)&wih_hi, d_wih_hi);
    cudaGetSymbolAddress((void**)&wih_lo, d_wih_lo);
    cudaGetSymbolAddress((void**)&whhp, d_whhp);
    cudaGetSymbolAddress((void**)&wo16, d_wo16);
    cudaGetSymbolAddress((void**)&bihp, d_bihp);
    cudaGetSymbolAddress((void**)&bhhp, d_bhhp);
    cudaGetSymbolAddress((void**)&ctx_hi, d_ctx_hi);
    cudaGetSymbolAddress((void**)&ctx_lo, d_ctx_lo);
    cudaGetSymbolAddress((void**)&xproj, d_xproj);
    cudaGetSymbolAddress((void**)&hall, d_hall);

    const int SMEM64  = 3 * 2 * 64 * 128;    // 49152
    const int SMEMBIG = 3 * 2 * 128 * 128;   // 98304
    const int SMEMREC = 26 * 64 * 128;       // 212992 (B 8 + A 16 chunks + xp 16KB)
    cudaFuncSetAttribute(k_g64<3, 0>, cudaFuncAttributeMaxDynamicSharedMemorySize, SMEM64);
    cudaFuncSetAttribute(k_g64<3, 2>, cudaFuncAttributeMaxDynamicSharedMemorySize, SMEM64);
    cudaFuncSetAttribute(k_rec, cudaFuncAttributeMaxDynamicSharedMemorySize, SMEMREC);
    cudaFuncSetAttribute(k_big, cudaFuncAttributeMaxDynamicSharedMemorySize, SMEMBIG);

    // launch 0: merged conversion + permutation
    k_prep<<<2048, 256>>>((const float4*)context, (const float4*)W_merge,
                          W_ih, W_hh, (const float4*)W_out, b_ih, b_hh);

    // launch 1: GEMM1  ctx = context @ Wm^T + b_merge (3-pass), split-store
    {
        dim3 g(HD / 64, NB / 64);  // (8,4)
        k_g64<3, 2><<<g, 128, SMEM64>>>(nullptr, ctx_hi, ctx_lo, HD,
            ctxin_hi, ctxin_lo, ctxin_hi,
            wm_hi, wm_hi, wm_lo,
            b_merge, CAT);
    }
    // launch 2: GEMM2  x_proj(perm) = ctx @ Wih_p^T + b_ih_p (3-pass)
    {
        dim3 g(G4 / 64, NB / 64);  // (32,4)
        k_g64<3, 0><<<g, 128, SMEM64>>>(xproj, nullptr, nullptr, G4,
            ctx_hi, ctx_lo, ctx_hi,
            wih_hi, wih_hi, wih_lo,
            bihp, HD);
    }
    // launch 3: persistent LSTM recurrence (all TT steps)
    {
        dim3 g(G4 / 64, NB / 64);  // (32,4) = 128 CTAs
        k_rec<<<g, 256, SMEMREC>>>(whhp, xproj, bhhp, hall);
    }
    // launch 4: big GEMM  out[2048,32000] = H_all @ Wo^T + b_out
    {
        dim3 g(VOC / 128, (NB * TT) / 128);  // (250,16)
        k_big<<<g, 128, SMEMBIG>>>(out, VOC, hall, wo16, b_out, HD);
    }
}